// round 1
// baseline (speedup 1.0000x reference)
#include <cuda_runtime.h>

#define NPTS 512
#define DIN 8192
#define HENC 2048
#define EMBD 256
#define HDEC 2048
#define BRW 128
#define NBRANCH 2
#define ETA_F 2.0f
#define RTOL_F 1e-4f
#define ATOL_F 1e-8f

// ---------------- scratch (no allocs allowed -> __device__ globals) ----------------
__device__ float g_h1[NPTS * HENC];
__device__ float g_lat[NPTS * EMBD];
__device__ float g_h2[NPTS * HDEC];
__device__ float g_D[NBRANCH][NPTS * NPTS];
__device__ float g_mst[NBRANCH][NPTS - 1];
__device__ float g_conn;
__device__ float g_rec;

__global__ void zero_kernel() { g_conn = 0.0f; g_rec = 0.0f; }

// ---------------- fp32 SGEMM: C = epilogue(A[MxK] @ B[KxN] + bias) ----------------
// BM=BN=64, BK=32, 256 threads, 4x4 register tile per thread.
// RELU: apply relu.  MSE: don't store; accumulate (X - C)^2 into g_rec.
template<bool RELU, bool MSE>
__global__ __launch_bounds__(256) void gemm_kernel(
    const float* __restrict__ A, const float* __restrict__ B,
    const float* __restrict__ bias, float* __restrict__ C,
    const float* __restrict__ X, int M, int Nn, int K)
{
    const int BM = 64, BN = 64, BK = 32;
    __shared__ float As[BK][BM + 4];   // transposed A tile, padded
    __shared__ float Bs[BK][BN];
    int tid = threadIdx.x;
    int ty = tid >> 4, tx = tid & 15;
    int bm = blockIdx.y * BM, bn = blockIdx.x * BN;
    float acc[4][4] = {};

    for (int k0 = 0; k0 < K; k0 += BK) {
        // A tile: 64 rows x 32 cols -> transposed into As[k][m]
        #pragma unroll
        for (int l = 0; l < 2; ++l) {
            int idx = tid + l * 256;          // float4 index
            int row = idx >> 3, cg = idx & 7; // 8 float4 per row
            float4 v = *(const float4*)&A[(size_t)(bm + row) * K + k0 + cg * 4];
            As[cg * 4 + 0][row] = v.x;
            As[cg * 4 + 1][row] = v.y;
            As[cg * 4 + 2][row] = v.z;
            As[cg * 4 + 3][row] = v.w;
        }
        // B tile: 32 rows x 64 cols, direct
        #pragma unroll
        for (int l = 0; l < 2; ++l) {
            int idx = tid + l * 256;
            int row = idx >> 4, cg = idx & 15; // 16 float4 per row
            *(float4*)&Bs[row][cg * 4] =
                *(const float4*)&B[(size_t)(k0 + row) * Nn + bn + cg * 4];
        }
        __syncthreads();
        #pragma unroll
        for (int k = 0; k < BK; ++k) {
            float4 af = *(const float4*)&As[k][ty * 4];
            float4 bf = *(const float4*)&Bs[k][tx * 4];
            float av[4] = {af.x, af.y, af.z, af.w};
            float bv[4] = {bf.x, bf.y, bf.z, bf.w};
            #pragma unroll
            for (int r = 0; r < 4; ++r)
                #pragma unroll
                for (int c = 0; c < 4; ++c)
                    acc[r][c] = fmaf(av[r], bv[c], acc[r][c]);
        }
        __syncthreads();
    }

    float lsum = 0.0f;
    #pragma unroll
    for (int r = 0; r < 4; ++r) {
        int row = bm + ty * 4 + r;
        #pragma unroll
        for (int c = 0; c < 4; ++c) {
            int col = bn + tx * 4 + c;
            float v = acc[r][c] + bias[col];
            if (RELU) v = fmaxf(v, 0.0f);
            if (MSE) {
                float dd = X[(size_t)row * Nn + col] - v;
                lsum = fmaf(dd, dd, lsum);
            } else {
                C[(size_t)row * Nn + col] = v;
            }
        }
    }
    if (MSE) {
        #pragma unroll
        for (int o = 16; o > 0; o >>= 1)
            lsum += __shfl_down_sync(0xffffffffu, lsum, o);
        __shared__ float wsum[8];
        if ((tid & 31) == 0) wsum[tid >> 5] = lsum;
        __syncthreads();
        if (tid == 0) {
            float s = 0.0f;
            #pragma unroll
            for (int w = 0; w < 8; ++w) s += wsum[w];
            atomicAdd(&g_rec, s);
        }
    }
}

// ---------------- pairwise distance matrix per branch (diff formula, == pdist) ----
// grid (16,16,2), block 256. 32x32 tile of D per block.
__global__ __launch_bounds__(256) void dist_kernel() {
    int br = blockIdx.z;
    int i0 = blockIdx.y * 32, j0 = blockIdx.x * 32;
    __shared__ float Li[32][BRW + 1];
    __shared__ float Lj[32][BRW + 1];
    int t = threadIdx.x;
    #pragma unroll
    for (int l = 0; l < 4; ++l) {
        int idx = t + l * 256;             // float4 index into 32x128 tile
        int r = idx >> 5, c4 = idx & 31;
        float4 v = *(const float4*)&g_lat[(size_t)(i0 + r) * EMBD + br * BRW + c4 * 4];
        Li[r][c4 * 4 + 0] = v.x; Li[r][c4 * 4 + 1] = v.y;
        Li[r][c4 * 4 + 2] = v.z; Li[r][c4 * 4 + 3] = v.w;
        float4 w = *(const float4*)&g_lat[(size_t)(j0 + r) * EMBD + br * BRW + c4 * 4];
        Lj[r][c4 * 4 + 0] = w.x; Lj[r][c4 * 4 + 1] = w.y;
        Lj[r][c4 * 4 + 2] = w.z; Lj[r][c4 * 4 + 3] = w.w;
    }
    __syncthreads();
    int tx = t & 31, ty = t >> 5;          // ty 0..7
    #pragma unroll
    for (int ii = 0; ii < 4; ++ii) {
        int il = ty * 4 + ii;
        float acc = 0.0f;
        #pragma unroll 16
        for (int k = 0; k < BRW; ++k) {
            float d = Li[il][k] - Lj[tx][k];
            acc = fmaf(d, d, acc);
        }
        g_D[br][(size_t)(i0 + il) * NPTS + j0 + tx] = sqrtf(acc);
    }
}

// ---------------- Prim MST per branch: 1 block of 512 threads ----------------
__global__ __launch_bounds__(512) void prim_kernel() {
    int br = blockIdx.x;
    const float* __restrict__ D = g_D[br];
    __shared__ float mind[NPTS];
    __shared__ int intree[NPTS];
    __shared__ float wv[16];
    __shared__ int wi[16];
    __shared__ int jsel;
    int t = threadIdx.x;
    mind[t] = D[t];                 // row 0
    intree[t] = (t == 0) ? 1 : 0;
    __syncthreads();
    for (int it = 0; it < NPTS - 1; ++it) {
        float v = intree[t] ? 3.402823466e38f : mind[t];
        int idx = t;
        #pragma unroll
        for (int o = 16; o > 0; o >>= 1) {
            float ov = __shfl_down_sync(0xffffffffu, v, o);
            int oi   = __shfl_down_sync(0xffffffffu, idx, o);
            if (ov < v || (ov == v && oi < idx)) { v = ov; idx = oi; }
        }
        if ((t & 31) == 0) { wv[t >> 5] = v; wi[t >> 5] = idx; }
        __syncthreads();                       // (A)
        if (t < 16) {
            float v2 = wv[t]; int i2 = wi[t];
            #pragma unroll
            for (int o = 8; o > 0; o >>= 1) {
                float ov = __shfl_down_sync(0x0000ffffu, v2, o);
                int oi   = __shfl_down_sync(0x0000ffffu, i2, o);
                if (ov < v2 || (ov == v2 && oi < i2)) { v2 = ov; i2 = oi; }
            }
            if (t == 0) { g_mst[br][it] = v2; jsel = i2; intree[i2] = 1; }
        }
        __syncthreads();                       // (B)
        int j = jsel;
        mind[t] = fminf(mind[t], D[(size_t)j * NPTS + t]);
        // no extra barrier needed: (A) next iter orders jsel/wv reuse
    }
}

// ---------------- connectivity loss: grid (511, 2), 512 threads --------------
__global__ __launch_bounds__(512) void conn_kernel() {
    int i = blockIdx.x;            // 0..510
    int br = blockIdx.y;
    __shared__ float mstv[NPTS - 1];
    __shared__ float bandv[NPTS - 1];
    int t = threadIdx.x;
    if (t < NPTS - 1) {
        float m = g_mst[br][t];
        mstv[t] = m;
        bandv[t] = ATOL_F + RTOL_F * fabsf(m);
    }
    __syncthreads();
    float contrib = 0.0f;
    if (t > i) {
        float d = g_D[br][(size_t)i * NPTS + t];
        bool hit = false;
        for (int m = 0; m < NPTS - 1; ++m) {
            if (fabsf(d - mstv[m]) <= bandv[m]) { hit = true; break; }
        }
        if (hit) contrib = fabsf(ETA_F - d);
    }
    #pragma unroll
    for (int o = 16; o > 0; o >>= 1)
        contrib += __shfl_down_sync(0xffffffffu, contrib, o);
    __shared__ float wsum[16];
    if ((t & 31) == 0) wsum[t >> 5] = contrib;
    __syncthreads();
    if (t == 0) {
        float s = 0.0f;
        #pragma unroll
        for (int w = 0; w < 16; ++w) s += wsum[w];
        atomicAdd(&g_conn, s);
    }
}

__global__ void final_kernel(float* out) {
    out[0] = g_rec / (float)((size_t)NPTS * (size_t)DIN) + g_conn;
}

// ---------------- launch ----------------
extern "C" void kernel_launch(void* const* d_in, const int* in_sizes, int n_in,
                              void* d_out, int out_size) {
    const float* x   = (const float*)d_in[0];
    const float* We1 = (const float*)d_in[1];
    const float* be1 = (const float*)d_in[2];
    const float* We2 = (const float*)d_in[3];
    const float* be2 = (const float*)d_in[4];
    const float* Wd1 = (const float*)d_in[5];
    const float* bd1 = (const float*)d_in[6];
    const float* Wd2 = (const float*)d_in[7];
    const float* bd2 = (const float*)d_in[8];
    float* out = (float*)d_out;

    float *h1, *lat, *h2;
    cudaGetSymbolAddress((void**)&h1, g_h1);
    cudaGetSymbolAddress((void**)&lat, g_lat);
    cudaGetSymbolAddress((void**)&h2, g_h2);

    zero_kernel<<<1, 1>>>();
    // encoder
    gemm_kernel<true,  false><<<dim3(HENC / 64, NPTS / 64), 256>>>(x,  We1, be1, h1,  nullptr, NPTS, HENC, DIN);
    gemm_kernel<false, false><<<dim3(EMBD / 64, NPTS / 64), 256>>>(h1, We2, be2, lat, nullptr, NPTS, EMBD, HENC);
    // topology branch
    dist_kernel<<<dim3(NPTS / 32, NPTS / 32, NBRANCH), 256>>>();
    prim_kernel<<<NBRANCH, NPTS>>>();
    conn_kernel<<<dim3(NPTS - 1, NBRANCH), NPTS>>>();
    // decoder + fused MSE
    gemm_kernel<true,  false><<<dim3(HDEC / 64, NPTS / 64), 256>>>(lat, Wd1, bd1, h2, nullptr, NPTS, HDEC, EMBD);
    gemm_kernel<false, true ><<<dim3(DIN  / 64, NPTS / 64), 256>>>(h2,  Wd2, bd2, nullptr, x,   NPTS, DIN,  HDEC);
    final_kernel<<<1, 1>>>(out);
}

// round 2
// speedup vs baseline: 1.4843x; 1.4843x over previous
#include <cuda_runtime.h>
#include <cuda_bf16.h>
#include <cstdint>

#define NPTS 512
#define DIN 8192
#define HENC 2048
#define EMBD 256
#define HDEC 2048
#define BRW 128
#define NBRANCH 2
#define ETA_F 2.0f
#define RTOL_F 1e-4f
#define ATOL_F 1e-8f

// ---------------- scratch ----------------
__device__ float g_h1[NPTS * HENC];
__device__ float g_lat[NPTS * EMBD];
__device__ __nv_bfloat16 g_lat_bf[NPTS * EMBD];
__device__ __nv_bfloat16 g_h2b[NPTS * HDEC];
__device__ __nv_bfloat16 g_Wd1b[EMBD * HDEC];
__device__ __nv_bfloat16 g_Wd2b[HDEC * DIN];
__device__ float g_D[NBRANCH][NPTS * NPTS];
__device__ float g_mst[NBRANCH][NPTS - 1];
__device__ float g_mst_sorted[NBRANCH][NPTS];
__device__ float g_conn;
__device__ float g_rec;

__global__ void zero_kernel() { g_conn = 0.0f; g_rec = 0.0f; }

// ---------------- helpers ----------------
__device__ __forceinline__ unsigned long long pk2(float x, float y) {
    unsigned long long d;
    asm("mov.b64 %0, {%1, %2};" : "=l"(d)
        : "r"(__float_as_uint(x)), "r"(__float_as_uint(y)));
    return d;
}
__device__ __forceinline__ void fma2(unsigned long long& d,
                                     unsigned long long a, unsigned long long b) {
    asm("fma.rn.f32x2 %0, %1, %2, %0;" : "+l"(d) : "l"(a), "l"(b));
}
__device__ __forceinline__ float plo(unsigned long long v) {
    return __uint_as_float((unsigned)(v & 0xffffffffULL));
}
__device__ __forceinline__ float phi(unsigned long long v) {
    return __uint_as_float((unsigned)(v >> 32));
}
__device__ __forceinline__ uint32_t s2u(const void* p) {
    uint32_t a;
    asm("{.reg .u64 t; cvta.to.shared.u64 t, %1; cvt.u32.u64 %0, t;}"
        : "=r"(a) : "l"(p));
    return a;
}
__device__ __forceinline__ void ldsm4(uint32_t* r, uint32_t addr) {
    asm volatile("ldmatrix.sync.aligned.m8n8.x4.shared.b16 {%0,%1,%2,%3}, [%4];"
                 : "=r"(r[0]), "=r"(r[1]), "=r"(r[2]), "=r"(r[3]) : "r"(addr));
}
__device__ __forceinline__ void ldsm4t(uint32_t* r, uint32_t addr) {
    asm volatile("ldmatrix.sync.aligned.m8n8.x4.trans.shared.b16 {%0,%1,%2,%3}, [%4];"
                 : "=r"(r[0]), "=r"(r[1]), "=r"(r[2]), "=r"(r[3]) : "r"(addr));
}
__device__ __forceinline__ void mma16816(float* c, const uint32_t* a, const uint32_t* b) {
    asm volatile(
        "mma.sync.aligned.m16n8k16.row.col.f32.bf16.bf16.f32 "
        "{%0,%1,%2,%3},{%4,%5,%6,%7},{%8,%9},{%0,%1,%2,%3};"
        : "+f"(c[0]), "+f"(c[1]), "+f"(c[2]), "+f"(c[3])
        : "r"(a[0]), "r"(a[1]), "r"(a[2]), "r"(a[3]), "r"(b[0]), "r"(b[1]));
}

// ---------------- fp32 GEMM via packed f32x2 FMA ----------------
// BM=64, BN=64*G, BK=32, 256 threads, double-buffered smem.
// thread (ty,tx): rows ty*4..+3, cols tx*4..+3 in each 64-col group g.
template<int G, bool RELU, bool DUAL>
__global__ __launch_bounds__(256) void sgemm_kernel(
    const float* __restrict__ A, const float* __restrict__ B,
    const float* __restrict__ bias, float* __restrict__ C,
    __nv_bfloat16* __restrict__ Cb, int M, int N, int K)
{
    const int BM = 64, BK = 32, BN = 64 * G;
    __shared__ float As[2][BK][BM];
    __shared__ float Bs[2][BK][BN];
    int tid = threadIdx.x;
    int ty = tid >> 4, tx = tid & 15;
    int bm = blockIdx.y * BM, bn = blockIdx.x * BN;

    unsigned long long acc[4][2 * G];
    #pragma unroll
    for (int r = 0; r < 4; ++r)
        #pragma unroll
        for (int c = 0; c < 2 * G; ++c) acc[r][c] = 0ULL;

    // A tile: 64 x 32 -> 512 float4, 2 per thread
    int arow[2], ac[2];
    #pragma unroll
    for (int l = 0; l < 2; ++l) { int idx = tid + l * 256; arow[l] = idx >> 3; ac[l] = idx & 7; }
    // B tile: 32 x BN -> 8*BN float4, 2G per thread
    const int F4PR = BN / 4;
    int brow[2 * G], bc[2 * G];
    #pragma unroll
    for (int l = 0; l < 2 * G; ++l) { int idx = tid + l * 256; brow[l] = idx / F4PR; bc[l] = idx % F4PR; }

    // preload chunk 0
    {
        #pragma unroll
        for (int l = 0; l < 2; ++l) {
            float4 v = *(const float4*)&A[(size_t)(bm + arow[l]) * K + ac[l] * 4];
            As[0][ac[l] * 4 + 0][arow[l]] = v.x;
            As[0][ac[l] * 4 + 1][arow[l]] = v.y;
            As[0][ac[l] * 4 + 2][arow[l]] = v.z;
            As[0][ac[l] * 4 + 3][arow[l]] = v.w;
        }
        #pragma unroll
        for (int l = 0; l < 2 * G; ++l)
            *(float4*)&Bs[0][brow[l]][bc[l] * 4] =
                *(const float4*)&B[(size_t)brow[l] * N + bn + bc[l] * 4];
    }
    __syncthreads();

    int cur = 0;
    for (int k0 = 0; k0 < K; k0 += BK) {
        float4 pa[2]; float4 pb[2 * G];
        bool more = (k0 + BK) < K;
        if (more) {
            #pragma unroll
            for (int l = 0; l < 2; ++l)
                pa[l] = *(const float4*)&A[(size_t)(bm + arow[l]) * K + k0 + BK + ac[l] * 4];
            #pragma unroll
            for (int l = 0; l < 2 * G; ++l)
                pb[l] = *(const float4*)&B[(size_t)(k0 + BK + brow[l]) * N + bn + bc[l] * 4];
        }
        #pragma unroll 8
        for (int k = 0; k < BK; ++k) {
            float4 av = *(const float4*)&As[cur][k][ty * 4];
            unsigned long long a2[4];
            a2[0] = pk2(av.x, av.x); a2[1] = pk2(av.y, av.y);
            a2[2] = pk2(av.z, av.z); a2[3] = pk2(av.w, av.w);
            #pragma unroll
            for (int g = 0; g < G; ++g) {
                float4 bv = *(const float4*)&Bs[cur][k][g * 64 + tx * 4];
                unsigned long long b0 = pk2(bv.x, bv.y), b1 = pk2(bv.z, bv.w);
                #pragma unroll
                for (int r = 0; r < 4; ++r) {
                    fma2(acc[r][g * 2 + 0], a2[r], b0);
                    fma2(acc[r][g * 2 + 1], a2[r], b1);
                }
            }
        }
        int nb = cur ^ 1;
        if (more) {
            #pragma unroll
            for (int l = 0; l < 2; ++l) {
                As[nb][ac[l] * 4 + 0][arow[l]] = pa[l].x;
                As[nb][ac[l] * 4 + 1][arow[l]] = pa[l].y;
                As[nb][ac[l] * 4 + 2][arow[l]] = pa[l].z;
                As[nb][ac[l] * 4 + 3][arow[l]] = pa[l].w;
            }
            #pragma unroll
            for (int l = 0; l < 2 * G; ++l)
                *(float4*)&Bs[nb][brow[l]][bc[l] * 4] = pb[l];
        }
        __syncthreads();
        cur = nb;
    }

    #pragma unroll
    for (int r = 0; r < 4; ++r) {
        int row = bm + ty * 4 + r;
        #pragma unroll
        for (int g = 0; g < G; ++g) {
            int cbase = bn + g * 64 + tx * 4;
            float4 bv = *(const float4*)&bias[cbase];
            float v0 = plo(acc[r][g * 2 + 0]) + bv.x;
            float v1 = phi(acc[r][g * 2 + 0]) + bv.y;
            float v2 = plo(acc[r][g * 2 + 1]) + bv.z;
            float v3 = phi(acc[r][g * 2 + 1]) + bv.w;
            if (RELU) {
                v0 = fmaxf(v0, 0.0f); v1 = fmaxf(v1, 0.0f);
                v2 = fmaxf(v2, 0.0f); v3 = fmaxf(v3, 0.0f);
            }
            *(float4*)&C[(size_t)row * N + cbase] = make_float4(v0, v1, v2, v3);
            if (DUAL) {
                __nv_bfloat162 h0 = __floats2bfloat162_rn(v0, v1);
                __nv_bfloat162 h1 = __floats2bfloat162_rn(v2, v3);
                __nv_bfloat162* p = (__nv_bfloat162*)&Cb[(size_t)row * N + cbase];
                p[0] = h0; p[1] = h1;
            }
        }
    }
}

// ---------------- fp32 -> bf16 convert ----------------
__global__ __launch_bounds__(256) void cvt_kernel(const float* __restrict__ s,
                                                  __nv_bfloat16* __restrict__ d, int n)
{
    int i = (blockIdx.x * 256 + threadIdx.x) * 8;
    if (i < n) {
        float4 a = *(const float4*)&s[i];
        float4 b = *(const float4*)&s[i + 4];
        __nv_bfloat162 h[4];
        h[0] = __floats2bfloat162_rn(a.x, a.y);
        h[1] = __floats2bfloat162_rn(a.z, a.w);
        h[2] = __floats2bfloat162_rn(b.x, b.y);
        h[3] = __floats2bfloat162_rn(b.z, b.w);
        *(uint4*)&d[i] = *(uint4*)h;
    }
}

// ---------------- bf16 tensor-core GEMM ----------------
// BM=128, BN=128, BK=32, 256 threads (8 warps, 4m x 2n), warp tile 32x64.
// MSE=false: out = relu(acc+bias) -> bf16 store to Cb.
// MSE=true:  accumulate (X - (acc+bias))^2 into g_rec.
#define PA 40    // As pitch (bf16)
#define PB 136   // Bs pitch (bf16)
template<bool MSE>
__global__ __launch_bounds__(256) void bgemm_kernel(
    const __nv_bfloat16* __restrict__ A, const __nv_bfloat16* __restrict__ B,
    const float* __restrict__ bias, __nv_bfloat16* __restrict__ Cb,
    const float* __restrict__ X, int M, int N, int K)
{
    const int BM = 128, BN = 128, BK = 32;
    __shared__ __nv_bfloat16 As[2][BM * PA];
    __shared__ __nv_bfloat16 Bs[2][BK * PB];
    int tid = threadIdx.x;
    int wid = tid >> 5, lane = tid & 31;
    int wm = (wid & 3) * 32, wn = (wid >> 2) * 64;
    int bm = blockIdx.y * BM, bn = blockIdx.x * BN;

    float acc[2][8][4];
    #pragma unroll
    for (int mt = 0; mt < 2; ++mt)
        #pragma unroll
        for (int nt = 0; nt < 8; ++nt)
            #pragma unroll
            for (int e = 0; e < 4; ++e) acc[mt][nt][e] = 0.0f;

    // A: 128x32 bf16 = 512 uint4, 2/thread: row=idx>>2, c=idx&3 (c*8 bf16)
    int ar[2], acg[2];
    #pragma unroll
    for (int l = 0; l < 2; ++l) { int idx = tid + l * 256; ar[l] = idx >> 2; acg[l] = idx & 3; }
    // B: 32x128 bf16 = 512 uint4, 2/thread: row=idx>>4, c=idx&15
    int br[2], bcg[2];
    #pragma unroll
    for (int l = 0; l < 2; ++l) { int idx = tid + l * 256; br[l] = idx >> 4; bcg[l] = idx & 15; }

    uint32_t asbase = s2u(&As[0][0]);
    uint32_t bsbase = s2u(&Bs[0][0]);

    // preload chunk 0
    #pragma unroll
    for (int l = 0; l < 2; ++l) {
        *(uint4*)&As[0][ar[l] * PA + acg[l] * 8] =
            *(const uint4*)&A[(size_t)(bm + ar[l]) * K + acg[l] * 8];
        *(uint4*)&Bs[0][br[l] * PB + bcg[l] * 8] =
            *(const uint4*)&B[(size_t)br[l] * N + bn + bcg[l] * 8];
    }
    __syncthreads();

    int sub = lane >> 3, lr = lane & 7;
    int cur = 0;
    for (int k0 = 0; k0 < K; k0 += BK) {
        uint4 pa[2], pb[2];
        bool more = (k0 + BK) < K;
        if (more) {
            #pragma unroll
            for (int l = 0; l < 2; ++l) {
                pa[l] = *(const uint4*)&A[(size_t)(bm + ar[l]) * K + k0 + BK + acg[l] * 8];
                pb[l] = *(const uint4*)&B[(size_t)(k0 + BK + br[l]) * N + bn + bcg[l] * 8];
            }
        }
        #pragma unroll
        for (int ks = 0; ks < BK; ks += 16) {
            uint32_t a[2][4], b[8][2];
            #pragma unroll
            for (int mt = 0; mt < 2; ++mt) {
                int row = wm + mt * 16 + (sub & 1) * 8 + lr;
                int kc = ks + (sub >> 1) * 8;
                ldsm4(a[mt], asbase + (uint32_t)(cur * BM * PA + row * PA + kc) * 2);
            }
            #pragma unroll
            for (int ng = 0; ng < 4; ++ng) {
                uint32_t r4[4];
                int krow = ks + (sub & 1) * 8 + lr;
                int ncol = wn + ng * 16 + (sub >> 1) * 8;
                ldsm4t(r4, bsbase + (uint32_t)(cur * BK * PB + krow * PB + ncol) * 2);
                b[ng * 2 + 0][0] = r4[0]; b[ng * 2 + 0][1] = r4[1];
                b[ng * 2 + 1][0] = r4[2]; b[ng * 2 + 1][1] = r4[3];
            }
            #pragma unroll
            for (int mt = 0; mt < 2; ++mt)
                #pragma unroll
                for (int nt = 0; nt < 8; ++nt)
                    mma16816(acc[mt][nt], a[mt], b[nt]);
        }
        int nb = cur ^ 1;
        if (more) {
            #pragma unroll
            for (int l = 0; l < 2; ++l) {
                *(uint4*)&As[nb][ar[l] * PA + acg[l] * 8] = pa[l];
                *(uint4*)&Bs[nb][br[l] * PB + bcg[l] * 8] = pb[l];
            }
        }
        __syncthreads();
        cur = nb;
    }

    float lsum = 0.0f;
    #pragma unroll
    for (int mt = 0; mt < 2; ++mt) {
        int row0 = bm + wm + mt * 16 + (lane >> 2);
        #pragma unroll
        for (int nt = 0; nt < 8; ++nt) {
            int col = bn + wn + nt * 8 + (lane & 3) * 2;
            float b0 = bias[col], b1 = bias[col + 1];
            #pragma unroll
            for (int h = 0; h < 2; ++h) {
                int row = row0 + h * 8;
                float v0 = acc[mt][nt][h * 2 + 0] + b0;
                float v1 = acc[mt][nt][h * 2 + 1] + b1;
                if (!MSE) {
                    v0 = fmaxf(v0, 0.0f); v1 = fmaxf(v1, 0.0f);
                    *(__nv_bfloat162*)&Cb[(size_t)row * N + col] = __floats2bfloat162_rn(v0, v1);
                } else {
                    float2 xv = *(const float2*)&X[(size_t)row * N + col];
                    float d0 = xv.x - v0, d1 = xv.y - v1;
                    lsum = fmaf(d0, d0, lsum);
                    lsum = fmaf(d1, d1, lsum);
                }
            }
        }
    }
    if (MSE) {
        #pragma unroll
        for (int o = 16; o > 0; o >>= 1)
            lsum += __shfl_down_sync(0xffffffffu, lsum, o);
        __shared__ float wsum[8];
        if (lane == 0) wsum[wid] = lsum;
        __syncthreads();
        if (tid == 0) {
            float s = 0.0f;
            #pragma unroll
            for (int w = 0; w < 8; ++w) s += wsum[w];
            atomicAdd(&g_rec, s);
        }
    }
}

// ---------------- pairwise distance matrix per branch ----------------
__global__ __launch_bounds__(256) void dist_kernel() {
    int brz = blockIdx.z;
    int i0 = blockIdx.y * 32, j0 = blockIdx.x * 32;
    __shared__ float Li[32][BRW + 1];
    __shared__ float Lj[32][BRW + 1];
    int t = threadIdx.x;
    #pragma unroll
    for (int l = 0; l < 4; ++l) {
        int idx = t + l * 256;
        int r = idx >> 5, c4 = idx & 31;
        float4 v = *(const float4*)&g_lat[(size_t)(i0 + r) * EMBD + brz * BRW + c4 * 4];
        Li[r][c4 * 4 + 0] = v.x; Li[r][c4 * 4 + 1] = v.y;
        Li[r][c4 * 4 + 2] = v.z; Li[r][c4 * 4 + 3] = v.w;
        float4 w = *(const float4*)&g_lat[(size_t)(j0 + r) * EMBD + brz * BRW + c4 * 4];
        Lj[r][c4 * 4 + 0] = w.x; Lj[r][c4 * 4 + 1] = w.y;
        Lj[r][c4 * 4 + 2] = w.z; Lj[r][c4 * 4 + 3] = w.w;
    }
    __syncthreads();
    int tx = t & 31, ty = t >> 5;
    #pragma unroll
    for (int ii = 0; ii < 4; ++ii) {
        int il = ty * 4 + ii;
        float acc = 0.0f;
        #pragma unroll 16
        for (int k = 0; k < BRW; ++k) {
            float d = Li[il][k] - Lj[tx][k];
            acc = fmaf(d, d, acc);
        }
        g_D[brz][(size_t)(i0 + il) * NPTS + j0 + tx] = sqrtf(acc);
    }
}

// ---------------- Prim MST per branch ----------------
__global__ __launch_bounds__(512) void prim_kernel() {
    int brz = blockIdx.x;
    const float* __restrict__ D = g_D[brz];
    __shared__ float mind[NPTS];
    __shared__ int intree[NPTS];
    __shared__ float wv[16];
    __shared__ int wi[16];
    __shared__ int jsel;
    int t = threadIdx.x;
    mind[t] = D[t];
    intree[t] = (t == 0) ? 1 : 0;
    __syncthreads();
    for (int it = 0; it < NPTS - 1; ++it) {
        float v = intree[t] ? 3.402823466e38f : mind[t];
        int idx = t;
        #pragma unroll
        for (int o = 16; o > 0; o >>= 1) {
            float ov = __shfl_down_sync(0xffffffffu, v, o);
            int oi   = __shfl_down_sync(0xffffffffu, idx, o);
            if (ov < v || (ov == v && oi < idx)) { v = ov; idx = oi; }
        }
        if ((t & 31) == 0) { wv[t >> 5] = v; wi[t >> 5] = idx; }
        __syncthreads();
        if (t < 16) {
            float v2 = wv[t]; int i2 = wi[t];
            #pragma unroll
            for (int o = 8; o > 0; o >>= 1) {
                float ov = __shfl_down_sync(0x0000ffffu, v2, o);
                int oi   = __shfl_down_sync(0x0000ffffu, i2, o);
                if (ov < v2 || (ov == v2 && oi < i2)) { v2 = ov; i2 = oi; }
            }
            if (t == 0) { g_mst[brz][it] = v2; jsel = i2; intree[i2] = 1; }
        }
        __syncthreads();
        int j = jsel;
        mind[t] = fminf(mind[t], D[(size_t)j * NPTS + t]);
    }
}

// ---------------- bitonic sort of MST lengths ----------------
__global__ __launch_bounds__(512) void sort_kernel() {
    int brz = blockIdx.x;
    __shared__ float s[NPTS];
    int t = threadIdx.x;
    s[t] = (t < NPTS - 1) ? g_mst[brz][t] : 3.402823466e38f;
    __syncthreads();
    for (int ksz = 2; ksz <= NPTS; ksz <<= 1) {
        for (int j = ksz >> 1; j > 0; j >>= 1) {
            int ixj = t ^ j;
            if (ixj > t) {
                float a = s[t], b = s[ixj];
                bool up = ((t & ksz) == 0);
                if ((a > b) == up) { s[t] = b; s[ixj] = a; }
            }
            __syncthreads();
        }
    }
    g_mst_sorted[brz][t] = s[t];
}

// ---------------- connectivity loss (binary search over sorted MST) ----------
__global__ __launch_bounds__(256) void conn_kernel() {
    int brz = blockIdx.y;
    __shared__ float s[NPTS];
    int t = threadIdx.x;
    s[t] = g_mst_sorted[brz][t];
    s[t + 256] = g_mst_sorted[brz][t + 256];
    __syncthreads();
    float lsum = 0.0f;
    for (int p = blockIdx.x * 256 + t; p < NPTS * NPTS; p += gridDim.x * 256) {
        int i = p >> 9, j = p & (NPTS - 1);
        if (j > i) {
            float d = g_D[brz][p];
            float lo = d - 0.004f, hi = d + 0.004f;
            // first index with s[idx] >= lo
            int l = 0, r = NPTS;
            while (l < r) {
                int m = (l + r) >> 1;
                if (s[m] < lo) l = m + 1; else r = m;
            }
            bool hit = false;
            while (l < NPTS - 1 && s[l] <= hi) {
                float m = s[l];
                if (fabsf(d - m) <= ATOL_F + RTOL_F * fabsf(m)) { hit = true; break; }
                ++l;
            }
            if (hit) lsum += fabsf(ETA_F - d);
        }
    }
    #pragma unroll
    for (int o = 16; o > 0; o >>= 1)
        lsum += __shfl_down_sync(0xffffffffu, lsum, o);
    __shared__ float wsum[8];
    if ((t & 31) == 0) wsum[t >> 5] = lsum;
    __syncthreads();
    if (t == 0) {
        float ss = 0.0f;
        #pragma unroll
        for (int w = 0; w < 8; ++w) ss += wsum[w];
        atomicAdd(&g_conn, ss);
    }
}

__global__ void final_kernel(float* out) {
    out[0] = g_rec / (float)((size_t)NPTS * (size_t)DIN) + g_conn;
}

// ---------------- launch ----------------
extern "C" void kernel_launch(void* const* d_in, const int* in_sizes, int n_in,
                              void* d_out, int out_size) {
    const float* x   = (const float*)d_in[0];
    const float* We1 = (const float*)d_in[1];
    const float* be1 = (const float*)d_in[2];
    const float* We2 = (const float*)d_in[3];
    const float* be2 = (const float*)d_in[4];
    const float* Wd1 = (const float*)d_in[5];
    const float* bd1 = (const float*)d_in[6];
    const float* Wd2 = (const float*)d_in[7];
    const float* bd2 = (const float*)d_in[8];
    float* out = (float*)d_out;

    float *h1, *lat;
    __nv_bfloat16 *latb, *h2b, *wd1b, *wd2b;
    cudaGetSymbolAddress((void**)&h1,   g_h1);
    cudaGetSymbolAddress((void**)&lat,  g_lat);
    cudaGetSymbolAddress((void**)&latb, g_lat_bf);
    cudaGetSymbolAddress((void**)&h2b,  g_h2b);
    cudaGetSymbolAddress((void**)&wd1b, g_Wd1b);
    cudaGetSymbolAddress((void**)&wd2b, g_Wd2b);

    zero_kernel<<<1, 1>>>();
    // weight conversions for decoder
    cvt_kernel<<<(EMBD * HDEC) / 2048, 256>>>(Wd1, wd1b, EMBD * HDEC);
    cvt_kernel<<<(HDEC * DIN) / 2048, 256>>>(Wd2, wd2b, HDEC * DIN);
    // encoder (fp32, f32x2 FMA)
    sgemm_kernel<2, true,  false><<<dim3(HENC / 128, NPTS / 64), 256>>>(x,  We1, be1, h1,  nullptr, NPTS, HENC, DIN);
    sgemm_kernel<1, false, true ><<<dim3(EMBD / 64,  NPTS / 64), 256>>>(h1, We2, be2, lat, latb,    NPTS, EMBD, HENC);
    // topology branch
    dist_kernel<<<dim3(NPTS / 32, NPTS / 32, NBRANCH), 256>>>();
    prim_kernel<<<NBRANCH, NPTS>>>();
    sort_kernel<<<NBRANCH, NPTS>>>();
    conn_kernel<<<dim3(64, NBRANCH), 256>>>();
    // decoder (bf16 tensor cores) + fused MSE
    bgemm_kernel<false><<<dim3(HDEC / 128, NPTS / 128), 256>>>(latb, wd1b, bd1, h2b, nullptr, NPTS, HDEC, EMBD);
    bgemm_kernel<true ><<<dim3(DIN  / 128, NPTS / 128), 256>>>(h2b,  wd2b, bd2, nullptr, x,   NPTS, DIN,  HDEC);
    final_kernel<<<1, 1>>>(out);
}

// round 4
// speedup vs baseline: 1.5374x; 1.0358x over previous
#include <cuda_runtime.h>
#include <cuda_bf16.h>
#include <cstdint>

#define NPTS 512
#define DIN 8192
#define HENC 2048
#define EMBD 256
#define HDEC 2048
#define BRW 128
#define NBRANCH 2
#define ETA_F 2.0f
#define RTOL_F 1e-4f
#define ATOL_F 1e-8f
#define SPLIT1 4
#define SPLIT2 8

// ---------------- scratch ----------------
__device__ float g_h1[NPTS * HENC];
__device__ float g_lat[NPTS * EMBD];
__device__ __nv_bfloat16 g_lat_bf[NPTS * EMBD];
__device__ __nv_bfloat16 g_h2b[NPTS * HDEC];
__device__ float g_part1[SPLIT1][NPTS * HENC];
__device__ float g_part2[SPLIT2][NPTS * EMBD];
__device__ float g_D[NBRANCH][NPTS * NPTS];
__device__ float g_mst[NBRANCH][NPTS - 1];
__device__ float g_mst_sorted[NBRANCH][NPTS];
__device__ float g_conn;
__device__ float g_rec;

__global__ void zero_kernel() { g_conn = 0.0f; g_rec = 0.0f; }

// ---------------- helpers ----------------
__device__ __forceinline__ void fma2(unsigned long long& d,
                                     unsigned long long a, unsigned long long b) {
    asm("fma.rn.f32x2 %0, %1, %2, %0;" : "+l"(d) : "l"(a), "l"(b));
}
__device__ __forceinline__ float plo(unsigned long long v) {
    return __uint_as_float((unsigned)(v & 0xffffffffULL));
}
__device__ __forceinline__ float phi(unsigned long long v) {
    return __uint_as_float((unsigned)(v >> 32));
}
__device__ __forceinline__ uint32_t s2u(const void* p) {
    uint32_t a;
    asm("{.reg .u64 t; cvta.to.shared.u64 t, %1; cvt.u32.u64 %0, t;}"
        : "=r"(a) : "l"(p));
    return a;
}
__device__ __forceinline__ void ldsm4(uint32_t* r, uint32_t addr) {
    asm volatile("ldmatrix.sync.aligned.m8n8.x4.shared.b16 {%0,%1,%2,%3}, [%4];"
                 : "=r"(r[0]), "=r"(r[1]), "=r"(r[2]), "=r"(r[3]) : "r"(addr));
}
__device__ __forceinline__ void ldsm4t(uint32_t* r, uint32_t addr) {
    asm volatile("ldmatrix.sync.aligned.m8n8.x4.trans.shared.b16 {%0,%1,%2,%3}, [%4];"
                 : "=r"(r[0]), "=r"(r[1]), "=r"(r[2]), "=r"(r[3]) : "r"(addr));
}
__device__ __forceinline__ void mma16816(float* c, const uint32_t* a, const uint32_t* b) {
    asm volatile(
        "mma.sync.aligned.m16n8k16.row.col.f32.bf16.bf16.f32 "
        "{%0,%1,%2,%3},{%4,%5,%6,%7},{%8,%9},{%0,%1,%2,%3};"
        : "+f"(c[0]), "+f"(c[1]), "+f"(c[2]), "+f"(c[3])
        : "r"(a[0]), "r"(a[1]), "r"(a[2]), "r"(a[3]), "r"(b[0]), "r"(b[1]));
}

// ---------------- fp32 split-K GEMM via packed f32x2 FMA ----------------
// BM=64, BN=64*G, BK=16, 256 threads. A tile stored DUPLICATED in smem so
// lds.64 yields (a,a); B pairs are natural lds.64. Inner loop = LDS64+FFMA2 only.
// Writes raw partial sums (no bias/relu) to P[blockIdx.z].
#define PAD2 (2 * 64 + 2)
template<int G>
__global__ __launch_bounds__(256) void sgemm_split(
    const float* __restrict__ A, const float* __restrict__ B,
    float* __restrict__ P, int M, int N, int K, int k_len)
{
    const int BM = 64, BK = 16, BN = 64 * G;
    __shared__ __align__(16) float As2[2][BK][PAD2];
    __shared__ __align__(16) float Bs[2][BK][BN];
    int tid = threadIdx.x;
    int ty = tid >> 4, tx = tid & 15;
    int bm = blockIdx.y * BM, bn = blockIdx.x * BN;
    int kb = blockIdx.z * k_len;
    P += (size_t)blockIdx.z * M * N;

    unsigned long long acc[4][2 * G];
    #pragma unroll
    for (int r = 0; r < 4; ++r)
        #pragma unroll
        for (int c = 0; c < 2 * G; ++c) acc[r][c] = 0ULL;

    // A: 64x16 tile = 256 float4 -> 1 per thread
    int arow = tid >> 2, ak4 = tid & 3;
    // B: 16xBN = 64G float4-rows -> G per thread
    const int F4PR = BN / 4;
    int brow[G], bc[G];
    #pragma unroll
    for (int l = 0; l < G; ++l) { int idx = tid + l * 256; brow[l] = idx / F4PR; bc[l] = idx % F4PR; }

    // preload chunk 0
    {
        float4 v = *(const float4*)&A[(size_t)(bm + arow) * K + kb + ak4 * 4];
        As2[0][ak4 * 4 + 0][2 * arow] = v.x; As2[0][ak4 * 4 + 0][2 * arow + 1] = v.x;
        As2[0][ak4 * 4 + 1][2 * arow] = v.y; As2[0][ak4 * 4 + 1][2 * arow + 1] = v.y;
        As2[0][ak4 * 4 + 2][2 * arow] = v.z; As2[0][ak4 * 4 + 2][2 * arow + 1] = v.z;
        As2[0][ak4 * 4 + 3][2 * arow] = v.w; As2[0][ak4 * 4 + 3][2 * arow + 1] = v.w;
        #pragma unroll
        for (int l = 0; l < G; ++l)
            *(float4*)&Bs[0][brow[l]][bc[l] * 4] =
                *(const float4*)&B[(size_t)(kb + brow[l]) * N + bn + bc[l] * 4];
    }
    __syncthreads();

    int cur = 0;
    for (int k0 = 0; k0 < k_len; k0 += BK) {
        float4 pa; float4 pb[G];
        bool more = (k0 + BK) < k_len;
        if (more) {
            pa = *(const float4*)&A[(size_t)(bm + arow) * K + kb + k0 + BK + ak4 * 4];
            #pragma unroll
            for (int l = 0; l < G; ++l)
                pb[l] = *(const float4*)&B[(size_t)(kb + k0 + BK + brow[l]) * N + bn + bc[l] * 4];
        }
        #pragma unroll
        for (int k = 0; k < BK; ++k) {
            unsigned long long a2[4];
            #pragma unroll
            for (int r = 0; r < 4; ++r)
                a2[r] = *(const unsigned long long*)&As2[cur][k][2 * (ty * 4 + r)];
            #pragma unroll
            for (int g = 0; g < G; ++g) {
                unsigned long long b0 = *(const unsigned long long*)&Bs[cur][k][g * 64 + tx * 4];
                unsigned long long b1 = *(const unsigned long long*)&Bs[cur][k][g * 64 + tx * 4 + 2];
                #pragma unroll
                for (int r = 0; r < 4; ++r) {
                    fma2(acc[r][g * 2 + 0], a2[r], b0);
                    fma2(acc[r][g * 2 + 1], a2[r], b1);
                }
            }
        }
        int nb = cur ^ 1;
        if (more) {
            As2[nb][ak4 * 4 + 0][2 * arow] = pa.x; As2[nb][ak4 * 4 + 0][2 * arow + 1] = pa.x;
            As2[nb][ak4 * 4 + 1][2 * arow] = pa.y; As2[nb][ak4 * 4 + 1][2 * arow + 1] = pa.y;
            As2[nb][ak4 * 4 + 2][2 * arow] = pa.z; As2[nb][ak4 * 4 + 2][2 * arow + 1] = pa.z;
            As2[nb][ak4 * 4 + 3][2 * arow] = pa.w; As2[nb][ak4 * 4 + 3][2 * arow + 1] = pa.w;
            #pragma unroll
            for (int l = 0; l < G; ++l)
                *(float4*)&Bs[nb][brow[l]][bc[l] * 4] = pb[l];
        }
        __syncthreads();
        cur = nb;
    }

    #pragma unroll
    for (int r = 0; r < 4; ++r) {
        int row = bm + ty * 4 + r;
        #pragma unroll
        for (int g = 0; g < G; ++g) {
            int cbase = bn + g * 64 + tx * 4;
            float4 o;
            o.x = plo(acc[r][g * 2 + 0]); o.y = phi(acc[r][g * 2 + 0]);
            o.z = plo(acc[r][g * 2 + 1]); o.w = phi(acc[r][g * 2 + 1]);
            *(float4*)&P[(size_t)row * N + cbase] = o;
        }
    }
}

// ---------------- split-K reductions ----------------
__global__ __launch_bounds__(256) void red1_kernel(const float* __restrict__ bias) {
    int i = (blockIdx.x * 256 + threadIdx.x) * 4;
    float4 s = *(const float4*)&g_part1[0][i];
    #pragma unroll
    for (int p = 1; p < SPLIT1; ++p) {
        float4 v = *(const float4*)&g_part1[p][i];
        s.x += v.x; s.y += v.y; s.z += v.z; s.w += v.w;
    }
    float4 b = *(const float4*)&bias[i & (HENC - 1)];
    s.x = fmaxf(s.x + b.x, 0.0f); s.y = fmaxf(s.y + b.y, 0.0f);
    s.z = fmaxf(s.z + b.z, 0.0f); s.w = fmaxf(s.w + b.w, 0.0f);
    *(float4*)&g_h1[i] = s;
}
__global__ __launch_bounds__(256) void red2_kernel(const float* __restrict__ bias) {
    int i = (blockIdx.x * 256 + threadIdx.x) * 4;
    float4 s = *(const float4*)&g_part2[0][i];
    #pragma unroll
    for (int p = 1; p < SPLIT2; ++p) {
        float4 v = *(const float4*)&g_part2[p][i];
        s.x += v.x; s.y += v.y; s.z += v.z; s.w += v.w;
    }
    float4 b = *(const float4*)&bias[i & (EMBD - 1)];
    s.x += b.x; s.y += b.y; s.z += b.z; s.w += b.w;
    *(float4*)&g_lat[i] = s;
    __nv_bfloat162 h0 = __floats2bfloat162_rn(s.x, s.y);
    __nv_bfloat162 h1 = __floats2bfloat162_rn(s.z, s.w);
    *(uint2*)&g_lat_bf[i] = make_uint2(*(uint32_t*)&h0, *(uint32_t*)&h1);
}

// ---------------- bf16 tensor-core GEMM (B converted fp32->bf16 in-flight) ----
#define PA 40
#define PB 136
template<bool MSE>
__global__ __launch_bounds__(256) void bgemm_kernel(
    const __nv_bfloat16* __restrict__ A, const float* __restrict__ B,
    const float* __restrict__ bias, __nv_bfloat16* __restrict__ Cb,
    const float* __restrict__ X, int M, int N, int K)
{
    const int BM = 128, BN = 128, BK = 32;
    __shared__ __nv_bfloat16 As[2][BM * PA];
    __shared__ __nv_bfloat16 Bs[2][BK * PB];
    int tid = threadIdx.x;
    int wid = tid >> 5, lane = tid & 31;
    int wm = (wid & 3) * 32, wn = (wid >> 2) * 64;
    int bm = blockIdx.y * BM, bn = blockIdx.x * BN;

    float acc[2][8][4];
    #pragma unroll
    for (int mt = 0; mt < 2; ++mt)
        #pragma unroll
        for (int nt = 0; nt < 8; ++nt)
            #pragma unroll
            for (int e = 0; e < 4; ++e) acc[mt][nt][e] = 0.0f;

    int ar[2], acg[2];
    #pragma unroll
    for (int l = 0; l < 2; ++l) { int idx = tid + l * 256; ar[l] = idx >> 2; acg[l] = idx & 3; }
    int br[2], bcg[2];
    #pragma unroll
    for (int l = 0; l < 2; ++l) { int idx = tid + l * 256; br[l] = idx >> 4; bcg[l] = idx & 15; }

    uint32_t asbase = s2u(&As[0][0]);
    uint32_t bsbase = s2u(&Bs[0][0]);

    // preload chunk 0
    #pragma unroll
    for (int l = 0; l < 2; ++l) {
        *(uint4*)&As[0][ar[l] * PA + acg[l] * 8] =
            *(const uint4*)&A[(size_t)(bm + ar[l]) * K + acg[l] * 8];
        float4 f0 = *(const float4*)&B[(size_t)br[l] * N + bn + bcg[l] * 8];
        float4 f1 = *(const float4*)&B[(size_t)br[l] * N + bn + bcg[l] * 8 + 4];
        __nv_bfloat162 h[4];
        h[0] = __floats2bfloat162_rn(f0.x, f0.y); h[1] = __floats2bfloat162_rn(f0.z, f0.w);
        h[2] = __floats2bfloat162_rn(f1.x, f1.y); h[3] = __floats2bfloat162_rn(f1.z, f1.w);
        *(uint4*)&Bs[0][br[l] * PB + bcg[l] * 8] = *(uint4*)h;
    }
    __syncthreads();

    int sub = lane >> 3, lr = lane & 7;
    int cur = 0;
    for (int k0 = 0; k0 < K; k0 += BK) {
        uint4 pa[2]; float4 pf0[2], pf1[2];
        bool more = (k0 + BK) < K;
        if (more) {
            #pragma unroll
            for (int l = 0; l < 2; ++l) {
                pa[l] = *(const uint4*)&A[(size_t)(bm + ar[l]) * K + k0 + BK + acg[l] * 8];
                pf0[l] = *(const float4*)&B[(size_t)(k0 + BK + br[l]) * N + bn + bcg[l] * 8];
                pf1[l] = *(const float4*)&B[(size_t)(k0 + BK + br[l]) * N + bn + bcg[l] * 8 + 4];
            }
        }
        #pragma unroll
        for (int ks = 0; ks < BK; ks += 16) {
            uint32_t a[2][4], b[8][2];
            #pragma unroll
            for (int mt = 0; mt < 2; ++mt) {
                int row = wm + mt * 16 + (sub & 1) * 8 + lr;
                int kc = ks + (sub >> 1) * 8;
                ldsm4(a[mt], asbase + (uint32_t)(cur * BM * PA + row * PA + kc) * 2);
            }
            #pragma unroll
            for (int ng = 0; ng < 4; ++ng) {
                uint32_t r4[4];
                int krow = ks + (sub & 1) * 8 + lr;
                int ncol = wn + ng * 16 + (sub >> 1) * 8;
                ldsm4t(r4, bsbase + (uint32_t)(cur * BK * PB + krow * PB + ncol) * 2);
                b[ng * 2 + 0][0] = r4[0]; b[ng * 2 + 0][1] = r4[1];
                b[ng * 2 + 1][0] = r4[2]; b[ng * 2 + 1][1] = r4[3];
            }
            #pragma unroll
            for (int mt = 0; mt < 2; ++mt)
                #pragma unroll
                for (int nt = 0; nt < 8; ++nt)
                    mma16816(acc[mt][nt], a[mt], b[nt]);
        }
        int nb = cur ^ 1;
        if (more) {
            #pragma unroll
            for (int l = 0; l < 2; ++l) {
                *(uint4*)&As[nb][ar[l] * PA + acg[l] * 8] = pa[l];
                __nv_bfloat162 h[4];
                h[0] = __floats2bfloat162_rn(pf0[l].x, pf0[l].y);
                h[1] = __floats2bfloat162_rn(pf0[l].z, pf0[l].w);
                h[2] = __floats2bfloat162_rn(pf1[l].x, pf1[l].y);
                h[3] = __floats2bfloat162_rn(pf1[l].z, pf1[l].w);
                *(uint4*)&Bs[nb][br[l] * PB + bcg[l] * 8] = *(uint4*)h;
            }
        }
        __syncthreads();
        cur = nb;
    }

    float lsum = 0.0f;
    #pragma unroll
    for (int mt = 0; mt < 2; ++mt) {
        int row0 = bm + wm + mt * 16 + (lane >> 2);
        #pragma unroll
        for (int nt = 0; nt < 8; ++nt) {
            int col = bn + wn + nt * 8 + (lane & 3) * 2;
            float b0 = bias[col], b1 = bias[col + 1];
            #pragma unroll
            for (int h = 0; h < 2; ++h) {
                int row = row0 + h * 8;
                float v0 = acc[mt][nt][h * 2 + 0] + b0;
                float v1 = acc[mt][nt][h * 2 + 1] + b1;
                if (!MSE) {
                    v0 = fmaxf(v0, 0.0f); v1 = fmaxf(v1, 0.0f);
                    *(__nv_bfloat162*)&Cb[(size_t)row * N + col] = __floats2bfloat162_rn(v0, v1);
                } else {
                    float2 xv = *(const float2*)&X[(size_t)row * N + col];
                    float d0 = xv.x - v0, d1 = xv.y - v1;
                    lsum = fmaf(d0, d0, lsum);
                    lsum = fmaf(d1, d1, lsum);
                }
            }
        }
    }
    if (MSE) {
        #pragma unroll
        for (int o = 16; o > 0; o >>= 1)
            lsum += __shfl_down_sync(0xffffffffu, lsum, o);
        __shared__ float wsum[8];
        if (lane == 0) wsum[wid] = lsum;
        __syncthreads();
        if (tid == 0) {
            float s = 0.0f;
            #pragma unroll
            for (int w = 0; w < 8; ++w) s += wsum[w];
            atomicAdd(&g_rec, s);
        }
    }
}

// ---------------- pairwise distance matrix per branch ----------------
__global__ __launch_bounds__(256) void dist_kernel() {
    int brz = blockIdx.z;
    int i0 = blockIdx.y * 32, j0 = blockIdx.x * 32;
    __shared__ float Li[32][BRW + 1];
    __shared__ float Lj[32][BRW + 1];
    int t = threadIdx.x;
    #pragma unroll
    for (int l = 0; l < 4; ++l) {
        int idx = t + l * 256;
        int r = idx >> 5, c4 = idx & 31;
        float4 v = *(const float4*)&g_lat[(size_t)(i0 + r) * EMBD + brz * BRW + c4 * 4];
        Li[r][c4 * 4 + 0] = v.x; Li[r][c4 * 4 + 1] = v.y;
        Li[r][c4 * 4 + 2] = v.z; Li[r][c4 * 4 + 3] = v.w;
        float4 w = *(const float4*)&g_lat[(size_t)(j0 + r) * EMBD + brz * BRW + c4 * 4];
        Lj[r][c4 * 4 + 0] = w.x; Lj[r][c4 * 4 + 1] = w.y;
        Lj[r][c4 * 4 + 2] = w.z; Lj[r][c4 * 4 + 3] = w.w;
    }
    __syncthreads();
    int tx = t & 31, ty = t >> 5;
    #pragma unroll
    for (int ii = 0; ii < 4; ++ii) {
        int il = ty * 4 + ii;
        float acc = 0.0f;
        #pragma unroll 16
        for (int k = 0; k < BRW; ++k) {
            float d = Li[il][k] - Lj[tx][k];
            acc = fmaf(d, d, acc);
        }
        g_D[brz][(size_t)(i0 + il) * NPTS + j0 + tx] = sqrtf(acc);
    }
}

// ---------------- Prim MST per branch ----------------
__global__ __launch_bounds__(512) void prim_kernel() {
    int brz = blockIdx.x;
    const float* __restrict__ D = g_D[brz];
    __shared__ float mind[NPTS];
    __shared__ int intree[NPTS];
    __shared__ float wv[16];
    __shared__ int wi[16];
    __shared__ int jsel;
    int t = threadIdx.x;
    mind[t] = D[t];
    intree[t] = (t == 0) ? 1 : 0;
    __syncthreads();
    for (int it = 0; it < NPTS - 1; ++it) {
        float v = intree[t] ? 3.402823466e38f : mind[t];
        int idx = t;
        #pragma unroll
        for (int o = 16; o > 0; o >>= 1) {
            float ov = __shfl_down_sync(0xffffffffu, v, o);
            int oi   = __shfl_down_sync(0xffffffffu, idx, o);
            if (ov < v || (ov == v && oi < idx)) { v = ov; idx = oi; }
        }
        if ((t & 31) == 0) { wv[t >> 5] = v; wi[t >> 5] = idx; }
        __syncthreads();
        if (t < 16) {
            float v2 = wv[t]; int i2 = wi[t];
            #pragma unroll
            for (int o = 8; o > 0; o >>= 1) {
                float ov = __shfl_down_sync(0x0000ffffu, v2, o);
                int oi   = __shfl_down_sync(0x0000ffffu, i2, o);
                if (ov < v2 || (ov == v2 && oi < i2)) { v2 = ov; i2 = oi; }
            }
            if (t == 0) { g_mst[brz][it] = v2; jsel = i2; intree[i2] = 1; }
        }
        __syncthreads();
        int j = jsel;
        mind[t] = fminf(mind[t], D[(size_t)j * NPTS + t]);
    }
}

// ---------------- bitonic sort of MST lengths ----------------
__global__ __launch_bounds__(512) void sort_kernel() {
    int brz = blockIdx.x;
    __shared__ float s[NPTS];
    int t = threadIdx.x;
    s[t] = (t < NPTS - 1) ? g_mst[brz][t] : 3.402823466e38f;
    __syncthreads();
    for (int ksz = 2; ksz <= NPTS; ksz <<= 1) {
        for (int j = ksz >> 1; j > 0; j >>= 1) {
            int ixj = t ^ j;
            if (ixj > t) {
                float a = s[t], b = s[ixj];
                bool up = ((t & ksz) == 0);
                if ((a > b) == up) { s[t] = b; s[ixj] = a; }
            }
            __syncthreads();
        }
    }
    g_mst_sorted[brz][t] = s[t];
}

// ---------------- connectivity loss (binary search over sorted MST) ----------
__global__ __launch_bounds__(256) void conn_kernel() {
    int brz = blockIdx.y;
    __shared__ float s[NPTS];
    int t = threadIdx.x;
    s[t] = g_mst_sorted[brz][t];
    s[t + 256] = g_mst_sorted[brz][t + 256];
    __syncthreads();
    float lsum = 0.0f;
    for (int p = blockIdx.x * 256 + t; p < NPTS * NPTS; p += gridDim.x * 256) {
        int i = p >> 9, j = p & (NPTS - 1);
        if (j > i) {
            float d = g_D[brz][p];
            float lo = d - 0.004f, hi = d + 0.004f;
            int l = 0, r = NPTS;
            while (l < r) {
                int m = (l + r) >> 1;
                if (s[m] < lo) l = m + 1; else r = m;
            }
            bool hit = false;
            while (l < NPTS - 1 && s[l] <= hi) {
                float m = s[l];
                if (fabsf(d - m) <= ATOL_F + RTOL_F * fabsf(m)) { hit = true; break; }
                ++l;
            }
            if (hit) lsum += fabsf(ETA_F - d);
        }
    }
    #pragma unroll
    for (int o = 16; o > 0; o >>= 1)
        lsum += __shfl_down_sync(0xffffffffu, lsum, o);
    __shared__ float wsum[8];
    if ((t & 31) == 0) wsum[t >> 5] = lsum;
    __syncthreads();
    if (t == 0) {
        float ss = 0.0f;
        #pragma unroll
        for (int w = 0; w < 8; ++w) ss += wsum[w];
        atomicAdd(&g_conn, ss);
    }
}

__global__ void final_kernel(float* out) {
    out[0] = g_rec / (float)((size_t)NPTS * (size_t)DIN) + g_conn;
}

// ---------------- launch ----------------
extern "C" void kernel_launch(void* const* d_in, const int* in_sizes, int n_in,
                              void* d_out, int out_size) {
    const float* x   = (const float*)d_in[0];
    const float* We1 = (const float*)d_in[1];
    const float* be1 = (const float*)d_in[2];
    const float* We2 = (const float*)d_in[3];
    const float* be2 = (const float*)d_in[4];
    const float* Wd1 = (const float*)d_in[5];
    const float* bd1 = (const float*)d_in[6];
    const float* Wd2 = (const float*)d_in[7];
    const float* bd2 = (const float*)d_in[8];
    float* out = (float*)d_out;

    float *h1, *p1, *p2;
    __nv_bfloat16 *latb, *h2b;
    cudaGetSymbolAddress((void**)&h1,   g_h1);
    cudaGetSymbolAddress((void**)&p1,   g_part1);
    cudaGetSymbolAddress((void**)&p2,   g_part2);
    cudaGetSymbolAddress((void**)&latb, g_lat_bf);
    cudaGetSymbolAddress((void**)&h2b,  g_h2b);

    zero_kernel<<<1, 1>>>();
    // encoder (fp32, packed FFMA2, deterministic split-K)
    sgemm_split<2><<<dim3(HENC / 128, NPTS / 64, SPLIT1), 256>>>(x, We1, p1, NPTS, HENC, DIN, DIN / SPLIT1);
    red1_kernel<<<NPTS * HENC / 1024, 256>>>(be1);
    sgemm_split<1><<<dim3(EMBD / 64, NPTS / 64, SPLIT2), 256>>>(h1, We2, p2, NPTS, EMBD, HENC, HENC / SPLIT2);
    red2_kernel<<<NPTS * EMBD / 1024, 256>>>(be2);
    // topology branch
    dist_kernel<<<dim3(NPTS / 32, NPTS / 32, NBRANCH), 256>>>();
    prim_kernel<<<NBRANCH, NPTS>>>();
    sort_kernel<<<NBRANCH, NPTS>>>();
    conn_kernel<<<dim3(64, NBRANCH), 256>>>();
    // decoder (bf16 tensor cores, B converted in-flight) + fused MSE
    bgemm_kernel<false><<<dim3(HDEC / 128, NPTS / 128), 256>>>(latb, Wd1, bd1, h2b, nullptr, NPTS, HDEC, EMBD);
    bgemm_kernel<true ><<<dim3(DIN  / 128, NPTS / 128), 256>>>(h2b,  Wd2, bd2, nullptr, x,   NPTS, DIN,  HDEC);
    final_kernel<<<1, 1>>>(out);
}

// round 5
// speedup vs baseline: 2.3747x; 1.5446x over previous
#include <cuda_runtime.h>
#include <cuda_bf16.h>
#include <cstdint>

#define NPTS 512
#define DIN 8192
#define HENC 2048
#define EMBD 256
#define HDEC 2048
#define BRW 128
#define NBRANCH 2
#define ETA_F 2.0f
#define RTOL_F 1e-4f
#define ATOL_F 1e-8f
#define SPLIT1 4
#define SPLIT2 8

// ---------------- scratch ----------------
__device__ float g_h1[NPTS * HENC];
__device__ float g_lat[NPTS * EMBD];
__device__ __nv_bfloat16 g_lat_bf[NPTS * EMBD];
__device__ __nv_bfloat16 g_h2b[NPTS * HDEC];
__device__ __nv_bfloat16 g_xhi[NPTS * DIN];
__device__ __nv_bfloat16 g_xlo[NPTS * DIN];
__device__ __nv_bfloat16 g_w1hi[DIN * HENC];
__device__ __nv_bfloat16 g_w1lo[DIN * HENC];
__device__ float g_part1[SPLIT1][NPTS * HENC];
__device__ float g_part2[SPLIT2][NPTS * EMBD];
__device__ float g_D[NBRANCH][NPTS * NPTS];
__device__ float g_mst[NBRANCH][NPTS - 1];
__device__ float g_mst_sorted[NBRANCH][NPTS];
__device__ float g_conn;
__device__ float g_rec;

__global__ void zero_kernel() { g_conn = 0.0f; g_rec = 0.0f; }

// ---------------- helpers ----------------
__device__ __forceinline__ void fma2(unsigned long long& d,
                                     unsigned long long a, unsigned long long b) {
    asm("fma.rn.f32x2 %0, %1, %2, %0;" : "+l"(d) : "l"(a), "l"(b));
}
__device__ __forceinline__ float plo(unsigned long long v) {
    return __uint_as_float((unsigned)(v & 0xffffffffULL));
}
__device__ __forceinline__ float phi(unsigned long long v) {
    return __uint_as_float((unsigned)(v >> 32));
}
__device__ __forceinline__ uint32_t s2u(const void* p) {
    uint32_t a;
    asm("{.reg .u64 t; cvta.to.shared.u64 t, %1; cvt.u32.u64 %0, t;}"
        : "=r"(a) : "l"(p));
    return a;
}
__device__ __forceinline__ void ldsm4(uint32_t* r, uint32_t addr) {
    asm volatile("ldmatrix.sync.aligned.m8n8.x4.shared.b16 {%0,%1,%2,%3}, [%4];"
                 : "=r"(r[0]), "=r"(r[1]), "=r"(r[2]), "=r"(r[3]) : "r"(addr));
}
__device__ __forceinline__ void ldsm4t(uint32_t* r, uint32_t addr) {
    asm volatile("ldmatrix.sync.aligned.m8n8.x4.trans.shared.b16 {%0,%1,%2,%3}, [%4];"
                 : "=r"(r[0]), "=r"(r[1]), "=r"(r[2]), "=r"(r[3]) : "r"(addr));
}
__device__ __forceinline__ void mma16816(float* c, const uint32_t* a, const uint32_t* b) {
    asm volatile(
        "mma.sync.aligned.m16n8k16.row.col.f32.bf16.bf16.f32 "
        "{%0,%1,%2,%3},{%4,%5,%6,%7},{%8,%9},{%0,%1,%2,%3};"
        : "+f"(c[0]), "+f"(c[1]), "+f"(c[2]), "+f"(c[3])
        : "r"(a[0]), "r"(a[1]), "r"(a[2]), "r"(a[3]), "r"(b[0]), "r"(b[1]));
}

// ---------------- fp32 -> (hi, lo) bf16 decomposition ----------------
__global__ __launch_bounds__(256) void cvt_split(const float* __restrict__ s,
                                                 __nv_bfloat16* __restrict__ hi,
                                                 __nv_bfloat16* __restrict__ lo, int n)
{
    int i = (blockIdx.x * 256 + threadIdx.x) * 4;
    if (i < n) {
        float4 a = *(const float4*)&s[i];
        __nv_bfloat16 h0 = __float2bfloat16_rn(a.x);
        __nv_bfloat16 h1 = __float2bfloat16_rn(a.y);
        __nv_bfloat16 h2 = __float2bfloat16_rn(a.z);
        __nv_bfloat16 h3 = __float2bfloat16_rn(a.w);
        __nv_bfloat16 l0 = __float2bfloat16_rn(a.x - __bfloat162float(h0));
        __nv_bfloat16 l1 = __float2bfloat16_rn(a.y - __bfloat162float(h1));
        __nv_bfloat16 l2 = __float2bfloat16_rn(a.z - __bfloat162float(h2));
        __nv_bfloat16 l3 = __float2bfloat16_rn(a.w - __bfloat162float(h3));
        __nv_bfloat16 hv[4] = {h0, h1, h2, h3};
        __nv_bfloat16 lv[4] = {l0, l1, l2, l3};
        *(uint2*)&hi[i] = *(uint2*)hv;
        *(uint2*)&lo[i] = *(uint2*)lv;
    }
}

// ---------------- bf16x3 tensor-core split-K GEMM (fp32-accurate) -------------
// BM=128, BN=128, BK=16, 256 threads (8 warps, 4m x 2n), warp tile 32x64.
// acc += Ahi*Bhi + Ahi*Blo + Alo*Bhi. Writes fp32 partials to P[blockIdx.z].
#define PA3 24     // As pitch (bf16) for BK=16
#define PB3 136    // Bs pitch (bf16) for BN=128
__global__ __launch_bounds__(256) void bgemm3_split(
    const __nv_bfloat16* __restrict__ Ahi, const __nv_bfloat16* __restrict__ Alo,
    const __nv_bfloat16* __restrict__ Bhi, const __nv_bfloat16* __restrict__ Blo,
    float* __restrict__ P, int M, int N, int K, int k_len)
{
    const int BM = 128, BN = 128, BK = 16;
    __shared__ __nv_bfloat16 As[2][2][BM * PA3];   // [buf][hi/lo]
    __shared__ __nv_bfloat16 Bs[2][2][BK * PB3];
    int tid = threadIdx.x;
    int wid = tid >> 5, lane = tid & 31;
    int wm = (wid & 3) * 32, wn = (wid >> 2) * 64;
    int bm = blockIdx.y * BM, bn = blockIdx.x * BN;
    int kb = blockIdx.z * k_len;
    P += (size_t)blockIdx.z * M * N;

    float acc[2][8][4];
    #pragma unroll
    for (int mt = 0; mt < 2; ++mt)
        #pragma unroll
        for (int nt = 0; nt < 8; ++nt)
            #pragma unroll
            for (int e = 0; e < 4; ++e) acc[mt][nt][e] = 0.0f;

    // A tile 128x16 bf16 = 256 uint4 -> 1/thread
    int ar = tid >> 1, acg = tid & 1;
    // B tile 16x128 bf16 = 256 uint4 -> 1/thread
    int br = tid >> 4, bcg = tid & 15;

    uint32_t asbase = s2u(&As[0][0][0]);
    uint32_t bsbase = s2u(&Bs[0][0][0]);

    // preload chunk 0
    *(uint4*)&As[0][0][ar * PA3 + acg * 8] =
        *(const uint4*)&Ahi[(size_t)(bm + ar) * K + kb + acg * 8];
    *(uint4*)&As[0][1][ar * PA3 + acg * 8] =
        *(const uint4*)&Alo[(size_t)(bm + ar) * K + kb + acg * 8];
    *(uint4*)&Bs[0][0][br * PB3 + bcg * 8] =
        *(const uint4*)&Bhi[(size_t)(kb + br) * N + bn + bcg * 8];
    *(uint4*)&Bs[0][1][br * PB3 + bcg * 8] =
        *(const uint4*)&Blo[(size_t)(kb + br) * N + bn + bcg * 8];
    __syncthreads();

    int sub = lane >> 3, lr = lane & 7;
    int cur = 0;
    for (int k0 = 0; k0 < k_len; k0 += BK) {
        uint4 pah, pal, pbh, pbl;
        bool more = (k0 + BK) < k_len;
        if (more) {
            pah = *(const uint4*)&Ahi[(size_t)(bm + ar) * K + kb + k0 + BK + acg * 8];
            pal = *(const uint4*)&Alo[(size_t)(bm + ar) * K + kb + k0 + BK + acg * 8];
            pbh = *(const uint4*)&Bhi[(size_t)(kb + k0 + BK + br) * N + bn + bcg * 8];
            pbl = *(const uint4*)&Blo[(size_t)(kb + k0 + BK + br) * N + bn + bcg * 8];
        }
        uint32_t ah[2][4], al[2][4], bh[8][2], bl[8][2];
        #pragma unroll
        for (int mt = 0; mt < 2; ++mt) {
            int row = wm + mt * 16 + (sub & 1) * 8 + lr;
            int kc = (sub >> 1) * 8;
            ldsm4(ah[mt], asbase + (uint32_t)((cur * 2 + 0) * BM * PA3 + row * PA3 + kc) * 2);
            ldsm4(al[mt], asbase + (uint32_t)((cur * 2 + 1) * BM * PA3 + row * PA3 + kc) * 2);
        }
        #pragma unroll
        for (int ng = 0; ng < 4; ++ng) {
            int krow = (sub & 1) * 8 + lr;
            int ncol = wn + ng * 16 + (sub >> 1) * 8;
            uint32_t r4[4];
            ldsm4t(r4, bsbase + (uint32_t)((cur * 2 + 0) * BK * PB3 + krow * PB3 + ncol) * 2);
            bh[ng * 2 + 0][0] = r4[0]; bh[ng * 2 + 0][1] = r4[1];
            bh[ng * 2 + 1][0] = r4[2]; bh[ng * 2 + 1][1] = r4[3];
            ldsm4t(r4, bsbase + (uint32_t)((cur * 2 + 1) * BK * PB3 + krow * PB3 + ncol) * 2);
            bl[ng * 2 + 0][0] = r4[0]; bl[ng * 2 + 0][1] = r4[1];
            bl[ng * 2 + 1][0] = r4[2]; bl[ng * 2 + 1][1] = r4[3];
        }
        #pragma unroll
        for (int mt = 0; mt < 2; ++mt)
            #pragma unroll
            for (int nt = 0; nt < 8; ++nt) {
                mma16816(acc[mt][nt], ah[mt], bh[nt]);
                mma16816(acc[mt][nt], ah[mt], bl[nt]);
                mma16816(acc[mt][nt], al[mt], bh[nt]);
            }
        int nb = cur ^ 1;
        if (more) {
            *(uint4*)&As[nb][0][ar * PA3 + acg * 8] = pah;
            *(uint4*)&As[nb][1][ar * PA3 + acg * 8] = pal;
            *(uint4*)&Bs[nb][0][br * PB3 + bcg * 8] = pbh;
            *(uint4*)&Bs[nb][1][br * PB3 + bcg * 8] = pbl;
        }
        __syncthreads();
        cur = nb;
    }

    #pragma unroll
    for (int mt = 0; mt < 2; ++mt) {
        int row0 = bm + wm + mt * 16 + (lane >> 2);
        #pragma unroll
        for (int nt = 0; nt < 8; ++nt) {
            int col = bn + wn + nt * 8 + (lane & 3) * 2;
            #pragma unroll
            for (int h = 0; h < 2; ++h) {
                int row = row0 + h * 8;
                *(float2*)&P[(size_t)row * N + col] =
                    make_float2(acc[mt][nt][h * 2 + 0], acc[mt][nt][h * 2 + 1]);
            }
        }
    }
}

// ---------------- fp32 split-K GEMM via packed f32x2 FMA (GEMM2) -------------
#define PAD2 (2 * 64 + 2)
template<int G>
__global__ __launch_bounds__(256) void sgemm_split(
    const float* __restrict__ A, const float* __restrict__ B,
    float* __restrict__ P, int M, int N, int K, int k_len)
{
    const int BM = 64, BK = 16, BN = 64 * G;
    __shared__ __align__(16) float As2[2][BK][PAD2];
    __shared__ __align__(16) float Bs[2][BK][BN];
    int tid = threadIdx.x;
    int ty = tid >> 4, tx = tid & 15;
    int bm = blockIdx.y * BM, bn = blockIdx.x * BN;
    int kb = blockIdx.z * k_len;
    P += (size_t)blockIdx.z * M * N;

    unsigned long long acc[4][2 * G];
    #pragma unroll
    for (int r = 0; r < 4; ++r)
        #pragma unroll
        for (int c = 0; c < 2 * G; ++c) acc[r][c] = 0ULL;

    int arow = tid >> 2, ak4 = tid & 3;
    const int F4PR = BN / 4;
    int brow[G], bc[G];
    #pragma unroll
    for (int l = 0; l < G; ++l) { int idx = tid + l * 256; brow[l] = idx / F4PR; bc[l] = idx % F4PR; }

    {
        float4 v = *(const float4*)&A[(size_t)(bm + arow) * K + kb + ak4 * 4];
        As2[0][ak4 * 4 + 0][2 * arow] = v.x; As2[0][ak4 * 4 + 0][2 * arow + 1] = v.x;
        As2[0][ak4 * 4 + 1][2 * arow] = v.y; As2[0][ak4 * 4 + 1][2 * arow + 1] = v.y;
        As2[0][ak4 * 4 + 2][2 * arow] = v.z; As2[0][ak4 * 4 + 2][2 * arow + 1] = v.z;
        As2[0][ak4 * 4 + 3][2 * arow] = v.w; As2[0][ak4 * 4 + 3][2 * arow + 1] = v.w;
        #pragma unroll
        for (int l = 0; l < G; ++l)
            *(float4*)&Bs[0][brow[l]][bc[l] * 4] =
                *(const float4*)&B[(size_t)(kb + brow[l]) * N + bn + bc[l] * 4];
    }
    __syncthreads();

    int cur = 0;
    for (int k0 = 0; k0 < k_len; k0 += BK) {
        float4 pa; float4 pb[G];
        bool more = (k0 + BK) < k_len;
        if (more) {
            pa = *(const float4*)&A[(size_t)(bm + arow) * K + kb + k0 + BK + ak4 * 4];
            #pragma unroll
            for (int l = 0; l < G; ++l)
                pb[l] = *(const float4*)&B[(size_t)(kb + k0 + BK + brow[l]) * N + bn + bc[l] * 4];
        }
        #pragma unroll
        for (int k = 0; k < BK; ++k) {
            unsigned long long a2[4];
            #pragma unroll
            for (int r = 0; r < 4; ++r)
                a2[r] = *(const unsigned long long*)&As2[cur][k][2 * (ty * 4 + r)];
            #pragma unroll
            for (int g = 0; g < G; ++g) {
                unsigned long long b0 = *(const unsigned long long*)&Bs[cur][k][g * 64 + tx * 4];
                unsigned long long b1 = *(const unsigned long long*)&Bs[cur][k][g * 64 + tx * 4 + 2];
                #pragma unroll
                for (int r = 0; r < 4; ++r) {
                    fma2(acc[r][g * 2 + 0], a2[r], b0);
                    fma2(acc[r][g * 2 + 1], a2[r], b1);
                }
            }
        }
        int nb = cur ^ 1;
        if (more) {
            As2[nb][ak4 * 4 + 0][2 * arow] = pa.x; As2[nb][ak4 * 4 + 0][2 * arow + 1] = pa.x;
            As2[nb][ak4 * 4 + 1][2 * arow] = pa.y; As2[nb][ak4 * 4 + 1][2 * arow + 1] = pa.y;
            As2[nb][ak4 * 4 + 2][2 * arow] = pa.z; As2[nb][ak4 * 4 + 2][2 * arow + 1] = pa.z;
            As2[nb][ak4 * 4 + 3][2 * arow] = pa.w; As2[nb][ak4 * 4 + 3][2 * arow + 1] = pa.w;
            #pragma unroll
            for (int l = 0; l < G; ++l)
                *(float4*)&Bs[nb][brow[l]][bc[l] * 4] = pb[l];
        }
        __syncthreads();
        cur = nb;
    }

    #pragma unroll
    for (int r = 0; r < 4; ++r) {
        int row = bm + ty * 4 + r;
        #pragma unroll
        for (int g = 0; g < G; ++g) {
            int cbase = bn + g * 64 + tx * 4;
            float4 o;
            o.x = plo(acc[r][g * 2 + 0]); o.y = phi(acc[r][g * 2 + 0]);
            o.z = plo(acc[r][g * 2 + 1]); o.w = phi(acc[r][g * 2 + 1]);
            *(float4*)&P[(size_t)row * N + cbase] = o;
        }
    }
}

// ---------------- split-K reductions ----------------
__global__ __launch_bounds__(256) void red1_kernel(const float* __restrict__ bias) {
    int i = (blockIdx.x * 256 + threadIdx.x) * 4;
    float4 s = *(const float4*)&g_part1[0][i];
    #pragma unroll
    for (int p = 1; p < SPLIT1; ++p) {
        float4 v = *(const float4*)&g_part1[p][i];
        s.x += v.x; s.y += v.y; s.z += v.z; s.w += v.w;
    }
    float4 b = *(const float4*)&bias[i & (HENC - 1)];
    s.x = fmaxf(s.x + b.x, 0.0f); s.y = fmaxf(s.y + b.y, 0.0f);
    s.z = fmaxf(s.z + b.z, 0.0f); s.w = fmaxf(s.w + b.w, 0.0f);
    *(float4*)&g_h1[i] = s;
}
__global__ __launch_bounds__(256) void red2_kernel(const float* __restrict__ bias) {
    int i = (blockIdx.x * 256 + threadIdx.x) * 4;
    float4 s = *(const float4*)&g_part2[0][i];
    #pragma unroll
    for (int p = 1; p < SPLIT2; ++p) {
        float4 v = *(const float4*)&g_part2[p][i];
        s.x += v.x; s.y += v.y; s.z += v.z; s.w += v.w;
    }
    float4 b = *(const float4*)&bias[i & (EMBD - 1)];
    s.x += b.x; s.y += b.y; s.z += b.z; s.w += b.w;
    *(float4*)&g_lat[i] = s;
    __nv_bfloat162 h0 = __floats2bfloat162_rn(s.x, s.y);
    __nv_bfloat162 h1 = __floats2bfloat162_rn(s.z, s.w);
    *(uint2*)&g_lat_bf[i] = make_uint2(*(uint32_t*)&h0, *(uint32_t*)&h1);
}

// ---------------- bf16 tensor-core GEMM (decoder; B converted in-flight) -----
#define PA 40
#define PB 136
template<bool MSE>
__global__ __launch_bounds__(256) void bgemm_kernel(
    const __nv_bfloat16* __restrict__ A, const float* __restrict__ B,
    const float* __restrict__ bias, __nv_bfloat16* __restrict__ Cb,
    const float* __restrict__ X, int M, int N, int K)
{
    const int BM = 128, BN = 128, BK = 32;
    __shared__ __nv_bfloat16 As[2][BM * PA];
    __shared__ __nv_bfloat16 Bs[2][BK * PB];
    int tid = threadIdx.x;
    int wid = tid >> 5, lane = tid & 31;
    int wm = (wid & 3) * 32, wn = (wid >> 2) * 64;
    int bm = blockIdx.y * BM, bn = blockIdx.x * BN;

    float acc[2][8][4];
    #pragma unroll
    for (int mt = 0; mt < 2; ++mt)
        #pragma unroll
        for (int nt = 0; nt < 8; ++nt)
            #pragma unroll
            for (int e = 0; e < 4; ++e) acc[mt][nt][e] = 0.0f;

    int ar[2], acg[2];
    #pragma unroll
    for (int l = 0; l < 2; ++l) { int idx = tid + l * 256; ar[l] = idx >> 2; acg[l] = idx & 3; }
    int br[2], bcg[2];
    #pragma unroll
    for (int l = 0; l < 2; ++l) { int idx = tid + l * 256; br[l] = idx >> 4; bcg[l] = idx & 15; }

    uint32_t asbase = s2u(&As[0][0]);
    uint32_t bsbase = s2u(&Bs[0][0]);

    #pragma unroll
    for (int l = 0; l < 2; ++l) {
        *(uint4*)&As[0][ar[l] * PA + acg[l] * 8] =
            *(const uint4*)&A[(size_t)(bm + ar[l]) * K + acg[l] * 8];
        float4 f0 = *(const float4*)&B[(size_t)br[l] * N + bn + bcg[l] * 8];
        float4 f1 = *(const float4*)&B[(size_t)br[l] * N + bn + bcg[l] * 8 + 4];
        __nv_bfloat162 h[4];
        h[0] = __floats2bfloat162_rn(f0.x, f0.y); h[1] = __floats2bfloat162_rn(f0.z, f0.w);
        h[2] = __floats2bfloat162_rn(f1.x, f1.y); h[3] = __floats2bfloat162_rn(f1.z, f1.w);
        *(uint4*)&Bs[0][br[l] * PB + bcg[l] * 8] = *(uint4*)h;
    }
    __syncthreads();

    int sub = lane >> 3, lr = lane & 7;
    int cur = 0;
    for (int k0 = 0; k0 < K; k0 += BK) {
        uint4 pa[2]; float4 pf0[2], pf1[2];
        bool more = (k0 + BK) < K;
        if (more) {
            #pragma unroll
            for (int l = 0; l < 2; ++l) {
                pa[l] = *(const uint4*)&A[(size_t)(bm + ar[l]) * K + k0 + BK + acg[l] * 8];
                pf0[l] = *(const float4*)&B[(size_t)(k0 + BK + br[l]) * N + bn + bcg[l] * 8];
                pf1[l] = *(const float4*)&B[(size_t)(k0 + BK + br[l]) * N + bn + bcg[l] * 8 + 4];
            }
        }
        #pragma unroll
        for (int ks = 0; ks < BK; ks += 16) {
            uint32_t a[2][4], b[8][2];
            #pragma unroll
            for (int mt = 0; mt < 2; ++mt) {
                int row = wm + mt * 16 + (sub & 1) * 8 + lr;
                int kc = ks + (sub >> 1) * 8;
                ldsm4(a[mt], asbase + (uint32_t)(cur * BM * PA + row * PA + kc) * 2);
            }
            #pragma unroll
            for (int ng = 0; ng < 4; ++ng) {
                uint32_t r4[4];
                int krow = ks + (sub & 1) * 8 + lr;
                int ncol = wn + ng * 16 + (sub >> 1) * 8;
                ldsm4t(r4, bsbase + (uint32_t)(cur * BK * PB + krow * PB + ncol) * 2);
                b[ng * 2 + 0][0] = r4[0]; b[ng * 2 + 0][1] = r4[1];
                b[ng * 2 + 1][0] = r4[2]; b[ng * 2 + 1][1] = r4[3];
            }
            #pragma unroll
            for (int mt = 0; mt < 2; ++mt)
                #pragma unroll
                for (int nt = 0; nt < 8; ++nt)
                    mma16816(acc[mt][nt], a[mt], b[nt]);
        }
        int nb = cur ^ 1;
        if (more) {
            #pragma unroll
            for (int l = 0; l < 2; ++l) {
                *(uint4*)&As[nb][ar[l] * PA + acg[l] * 8] = pa[l];
                __nv_bfloat162 h[4];
                h[0] = __floats2bfloat162_rn(pf0[l].x, pf0[l].y);
                h[1] = __floats2bfloat162_rn(pf0[l].z, pf0[l].w);
                h[2] = __floats2bfloat162_rn(pf1[l].x, pf1[l].y);
                h[3] = __floats2bfloat162_rn(pf1[l].z, pf1[l].w);
                *(uint4*)&Bs[nb][br[l] * PB + bcg[l] * 8] = *(uint4*)h;
            }
        }
        __syncthreads();
        cur = nb;
    }

    float lsum = 0.0f;
    #pragma unroll
    for (int mt = 0; mt < 2; ++mt) {
        int row0 = bm + wm + mt * 16 + (lane >> 2);
        #pragma unroll
        for (int nt = 0; nt < 8; ++nt) {
            int col = bn + wn + nt * 8 + (lane & 3) * 2;
            float b0 = bias[col], b1 = bias[col + 1];
            #pragma unroll
            for (int h = 0; h < 2; ++h) {
                int row = row0 + h * 8;
                float v0 = acc[mt][nt][h * 2 + 0] + b0;
                float v1 = acc[mt][nt][h * 2 + 1] + b1;
                if (!MSE) {
                    v0 = fmaxf(v0, 0.0f); v1 = fmaxf(v1, 0.0f);
                    *(__nv_bfloat162*)&Cb[(size_t)row * N + col] = __floats2bfloat162_rn(v0, v1);
                } else {
                    float2 xv = *(const float2*)&X[(size_t)row * N + col];
                    float d0 = xv.x - v0, d1 = xv.y - v1;
                    lsum = fmaf(d0, d0, lsum);
                    lsum = fmaf(d1, d1, lsum);
                }
            }
        }
    }
    if (MSE) {
        #pragma unroll
        for (int o = 16; o > 0; o >>= 1)
            lsum += __shfl_down_sync(0xffffffffu, lsum, o);
        __shared__ float wsum[8];
        if (lane == 0) wsum[wid] = lsum;
        __syncthreads();
        if (tid == 0) {
            float s = 0.0f;
            #pragma unroll
            for (int w = 0; w < 8; ++w) s += wsum[w];
            atomicAdd(&g_rec, s);
        }
    }
}

// ---------------- pairwise distance matrix per branch ----------------
__global__ __launch_bounds__(256) void dist_kernel() {
    int brz = blockIdx.z;
    int i0 = blockIdx.y * 32, j0 = blockIdx.x * 32;
    __shared__ float Li[32][BRW + 1];
    __shared__ float Lj[32][BRW + 1];
    int t = threadIdx.x;
    #pragma unroll
    for (int l = 0; l < 4; ++l) {
        int idx = t + l * 256;
        int r = idx >> 5, c4 = idx & 31;
        float4 v = *(const float4*)&g_lat[(size_t)(i0 + r) * EMBD + brz * BRW + c4 * 4];
        Li[r][c4 * 4 + 0] = v.x; Li[r][c4 * 4 + 1] = v.y;
        Li[r][c4 * 4 + 2] = v.z; Li[r][c4 * 4 + 3] = v.w;
        float4 w = *(const float4*)&g_lat[(size_t)(j0 + r) * EMBD + brz * BRW + c4 * 4];
        Lj[r][c4 * 4 + 0] = w.x; Lj[r][c4 * 4 + 1] = w.y;
        Lj[r][c4 * 4 + 2] = w.z; Lj[r][c4 * 4 + 3] = w.w;
    }
    __syncthreads();
    int tx = t & 31, ty = t >> 5;
    #pragma unroll
    for (int ii = 0; ii < 4; ++ii) {
        int il = ty * 4 + ii;
        float acc = 0.0f;
        #pragma unroll 16
        for (int k = 0; k < BRW; ++k) {
            float d = Li[il][k] - Lj[tx][k];
            acc = fmaf(d, d, acc);
        }
        g_D[brz][(size_t)(i0 + il) * NPTS + j0 + tx] = sqrtf(acc);
    }
}

// ---------------- Prim MST per branch ----------------
__global__ __launch_bounds__(512) void prim_kernel() {
    int brz = blockIdx.x;
    const float* __restrict__ D = g_D[brz];
    __shared__ float mind[NPTS];
    __shared__ int intree[NPTS];
    __shared__ float wv[16];
    __shared__ int wi[16];
    __shared__ int jsel;
    int t = threadIdx.x;
    mind[t] = D[t];
    intree[t] = (t == 0) ? 1 : 0;
    __syncthreads();
    for (int it = 0; it < NPTS - 1; ++it) {
        float v = intree[t] ? 3.402823466e38f : mind[t];
        int idx = t;
        #pragma unroll
        for (int o = 16; o > 0; o >>= 1) {
            float ov = __shfl_down_sync(0xffffffffu, v, o);
            int oi   = __shfl_down_sync(0xffffffffu, idx, o);
            if (ov < v || (ov == v && oi < idx)) { v = ov; idx = oi; }
        }
        if ((t & 31) == 0) { wv[t >> 5] = v; wi[t >> 5] = idx; }
        __syncthreads();
        if (t < 16) {
            float v2 = wv[t]; int i2 = wi[t];
            #pragma unroll
            for (int o = 8; o > 0; o >>= 1) {
                float ov = __shfl_down_sync(0x0000ffffu, v2, o);
                int oi   = __shfl_down_sync(0x0000ffffu, i2, o);
                if (ov < v2 || (ov == v2 && oi < i2)) { v2 = ov; i2 = oi; }
            }
            if (t == 0) { g_mst[brz][it] = v2; jsel = i2; intree[i2] = 1; }
        }
        __syncthreads();
        int j = jsel;
        mind[t] = fminf(mind[t], D[(size_t)j * NPTS + t]);
    }
}

// ---------------- bitonic sort of MST lengths ----------------
__global__ __launch_bounds__(512) void sort_kernel() {
    int brz = blockIdx.x;
    __shared__ float s[NPTS];
    int t = threadIdx.x;
    s[t] = (t < NPTS - 1) ? g_mst[brz][t] : 3.402823466e38f;
    __syncthreads();
    for (int ksz = 2; ksz <= NPTS; ksz <<= 1) {
        for (int j = ksz >> 1; j > 0; j >>= 1) {
            int ixj = t ^ j;
            if (ixj > t) {
                float a = s[t], b = s[ixj];
                bool up = ((t & ksz) == 0);
                if ((a > b) == up) { s[t] = b; s[ixj] = a; }
            }
            __syncthreads();
        }
    }
    g_mst_sorted[brz][t] = s[t];
}

// ---------------- connectivity loss (binary search over sorted MST) ----------
__global__ __launch_bounds__(256) void conn_kernel() {
    int brz = blockIdx.y;
    __shared__ float s[NPTS];
    int t = threadIdx.x;
    s[t] = g_mst_sorted[brz][t];
    s[t + 256] = g_mst_sorted[brz][t + 256];
    __syncthreads();
    float lsum = 0.0f;
    for (int p = blockIdx.x * 256 + t; p < NPTS * NPTS; p += gridDim.x * 256) {
        int i = p >> 9, j = p & (NPTS - 1);
        if (j > i) {
            float d = g_D[brz][p];
            float lo = d - 0.004f, hi = d + 0.004f;
            int l = 0, r = NPTS;
            while (l < r) {
                int m = (l + r) >> 1;
                if (s[m] < lo) l = m + 1; else r = m;
            }
            bool hit = false;
            while (l < NPTS - 1 && s[l] <= hi) {
                float m = s[l];
                if (fabsf(d - m) <= ATOL_F + RTOL_F * fabsf(m)) { hit = true; break; }
                ++l;
            }
            if (hit) lsum += fabsf(ETA_F - d);
        }
    }
    #pragma unroll
    for (int o = 16; o > 0; o >>= 1)
        lsum += __shfl_down_sync(0xffffffffu, lsum, o);
    __shared__ float wsum[8];
    if ((t & 31) == 0) wsum[t >> 5] = lsum;
    __syncthreads();
    if (t == 0) {
        float ss = 0.0f;
        #pragma unroll
        for (int w = 0; w < 8; ++w) ss += wsum[w];
        atomicAdd(&g_conn, ss);
    }
}

__global__ void final_kernel(float* out) {
    out[0] = g_rec / (float)((size_t)NPTS * (size_t)DIN) + g_conn;
}

// ---------------- launch ----------------
extern "C" void kernel_launch(void* const* d_in, const int* in_sizes, int n_in,
                              void* d_out, int out_size) {
    const float* x   = (const float*)d_in[0];
    const float* We1 = (const float*)d_in[1];
    const float* be1 = (const float*)d_in[2];
    const float* We2 = (const float*)d_in[3];
    const float* be2 = (const float*)d_in[4];
    const float* Wd1 = (const float*)d_in[5];
    const float* bd1 = (const float*)d_in[6];
    const float* Wd2 = (const float*)d_in[7];
    const float* bd2 = (const float*)d_in[8];
    float* out = (float*)d_out;

    float *h1, *p1, *p2;
    __nv_bfloat16 *latb, *h2b, *xhi, *xlo, *w1hi, *w1lo;
    cudaGetSymbolAddress((void**)&h1,   g_h1);
    cudaGetSymbolAddress((void**)&p1,   g_part1);
    cudaGetSymbolAddress((void**)&p2,   g_part2);
    cudaGetSymbolAddress((void**)&latb, g_lat_bf);
    cudaGetSymbolAddress((void**)&h2b,  g_h2b);
    cudaGetSymbolAddress((void**)&xhi,  g_xhi);
    cudaGetSymbolAddress((void**)&xlo,  g_xlo);
    cudaGetSymbolAddress((void**)&w1hi, g_w1hi);
    cudaGetSymbolAddress((void**)&w1lo, g_w1lo);

    zero_kernel<<<1, 1>>>();
    // hi/lo decomposition of x and We1 for bf16x3 encoder GEMM
    cvt_split<<<(NPTS * DIN) / 1024, 256>>>(x, xhi, xlo, NPTS * DIN);
    cvt_split<<<(DIN * HENC) / 1024, 256>>>(We1, w1hi, w1lo, DIN * HENC);
    // encoder GEMM1: bf16x3 tensor cores, deterministic split-K
    bgemm3_split<<<dim3(HENC / 128, NPTS / 128, SPLIT1), 256>>>(
        xhi, xlo, w1hi, w1lo, p1, NPTS, HENC, DIN, DIN / SPLIT1);
    red1_kernel<<<NPTS * HENC / 1024, 256>>>(be1);
    // encoder GEMM2: fp32 FFMA2 split-K (small)
    sgemm_split<1><<<dim3(EMBD / 64, NPTS / 64, SPLIT2), 256>>>(h1, We2, p2, NPTS, EMBD, HENC, HENC / SPLIT2);
    red2_kernel<<<NPTS * EMBD / 1024, 256>>>(be2);
    // topology branch
    dist_kernel<<<dim3(NPTS / 32, NPTS / 32, NBRANCH), 256>>>();
    prim_kernel<<<NBRANCH, NPTS>>>();
    sort_kernel<<<NBRANCH, NPTS>>>();
    conn_kernel<<<dim3(64, NBRANCH), 256>>>();
    // decoder (bf16 tensor cores) + fused MSE
    bgemm_kernel<false><<<dim3(HDEC / 128, NPTS / 128), 256>>>(latb, Wd1, bd1, h2b, nullptr, NPTS, HDEC, EMBD);
    bgemm_kernel<true ><<<dim3(DIN  / 128, NPTS / 128), 256>>>(h2b,  Wd2, bd2, nullptr, x,   NPTS, DIN,  HDEC);
    final_kernel<<<1, 1>>>(out);
}

// round 6
// speedup vs baseline: 2.9559x; 1.2447x over previous
#include <cuda_runtime.h>
#include <cuda_bf16.h>
#include <cstdint>

#define NPTS 512
#define DIN 8192
#define HENC 2048
#define EMBD 256
#define HDEC 2048
#define BRW 128
#define NBRANCH 2
#define ETA_F 2.0f
#define RTOL_F 1e-4f
#define ATOL_F 1e-8f
#define SPLIT1 8
#define SPLIT2 8

// ---------------- scratch ----------------
__device__ float g_h1[NPTS * HENC];
__device__ float g_lat[NPTS * EMBD];
__device__ __nv_bfloat16 g_lat_bf[NPTS * EMBD];
__device__ __nv_bfloat16 g_h2b[NPTS * HDEC];
__device__ float g_part1[SPLIT1][NPTS * HENC];
__device__ float g_part2[SPLIT2][NPTS * EMBD];
__device__ float g_D[NBRANCH][NPTS * NPTS];
__device__ float g_mst[NBRANCH][NPTS - 1];
__device__ float g_mst_sorted[NBRANCH][NPTS];
__device__ float g_conn;
__device__ float g_rec;

__global__ void zero_kernel() { g_conn = 0.0f; g_rec = 0.0f; }

// ---------------- helpers ----------------
__device__ __forceinline__ uint32_t s2u(const void* p) {
    uint32_t a;
    asm("{.reg .u64 t; cvta.to.shared.u64 t, %1; cvt.u32.u64 %0, t;}"
        : "=r"(a) : "l"(p));
    return a;
}
__device__ __forceinline__ void ldsm4(uint32_t* r, uint32_t addr) {
    asm volatile("ldmatrix.sync.aligned.m8n8.x4.shared.b16 {%0,%1,%2,%3}, [%4];"
                 : "=r"(r[0]), "=r"(r[1]), "=r"(r[2]), "=r"(r[3]) : "r"(addr));
}
__device__ __forceinline__ void ldsm4t(uint32_t* r, uint32_t addr) {
    asm volatile("ldmatrix.sync.aligned.m8n8.x4.trans.shared.b16 {%0,%1,%2,%3}, [%4];"
                 : "=r"(r[0]), "=r"(r[1]), "=r"(r[2]), "=r"(r[3]) : "r"(addr));
}
__device__ __forceinline__ void mma16816(float* c, const uint32_t* a, const uint32_t* b) {
    asm volatile(
        "mma.sync.aligned.m16n8k16.row.col.f32.bf16.bf16.f32 "
        "{%0,%1,%2,%3},{%4,%5,%6,%7},{%8,%9},{%0,%1,%2,%3};"
        : "+f"(c[0]), "+f"(c[1]), "+f"(c[2]), "+f"(c[3])
        : "r"(a[0]), "r"(a[1]), "r"(a[2]), "r"(a[3]), "r"(b[0]), "r"(b[1]));
}
// fp32x4 -> 4 hi bf16 + 4 lo bf16
__device__ __forceinline__ void split_f4(float4 v, __nv_bfloat16* h, __nv_bfloat16* l) {
    h[0] = __float2bfloat16_rn(v.x); l[0] = __float2bfloat16_rn(v.x - __bfloat162float(h[0]));
    h[1] = __float2bfloat16_rn(v.y); l[1] = __float2bfloat16_rn(v.y - __bfloat162float(h[1]));
    h[2] = __float2bfloat16_rn(v.z); l[2] = __float2bfloat16_rn(v.z - __bfloat162float(h[2]));
    h[3] = __float2bfloat16_rn(v.w); l[3] = __float2bfloat16_rn(v.w - __bfloat162float(h[3]));
}

// ---------------- bf16x3 tensor-core split-K GEMM, fp32 in, fused hi/lo split --
// BM=128, BN=128, BK=16, 256 threads (8 warps, 4m x 2n), warp tile 32x64.
// acc += Ahi*Bhi + Ahi*Blo + Alo*Bhi. Writes fp32 partials to P[blockIdx.z].
#define PA3 24     // As pitch (bf16) for BK=16
#define PB3 136    // Bs pitch (bf16) for BN=128
__global__ __launch_bounds__(256, 2) void bgemm3_split(
    const float* __restrict__ A, const float* __restrict__ B,
    float* __restrict__ P, int M, int N, int K, int k_len)
{
    const int BM = 128, BN = 128, BK = 16;
    __shared__ __nv_bfloat16 As[2][2][BM * PA3];   // [buf][hi/lo]
    __shared__ __nv_bfloat16 Bs[2][2][BK * PB3];
    int tid = threadIdx.x;
    int wid = tid >> 5, lane = tid & 31;
    int wm = (wid & 3) * 32, wn = (wid >> 2) * 64;
    int bm = blockIdx.y * BM, bn = blockIdx.x * BN;
    int kb = blockIdx.z * k_len;
    P += (size_t)blockIdx.z * M * N;

    float acc[2][8][4];
    #pragma unroll
    for (int mt = 0; mt < 2; ++mt)
        #pragma unroll
        for (int nt = 0; nt < 8; ++nt)
            #pragma unroll
            for (int e = 0; e < 4; ++e) acc[mt][nt][e] = 0.0f;

    // A tile 128x16 fp32 = 512 float4 -> 2/thread: row = idx>>2, c4 = idx&3
    int ar[2], ac4[2];
    #pragma unroll
    for (int l = 0; l < 2; ++l) { int idx = tid + l * 256; ar[l] = idx >> 2; ac4[l] = idx & 3; }
    // B tile 16x128 fp32 = 512 float4 -> 2/thread: row = idx>>5, c4 = idx&31
    int br[2], bc4[2];
    #pragma unroll
    for (int l = 0; l < 2; ++l) { int idx = tid + l * 256; br[l] = idx >> 5; bc4[l] = idx & 31; }

    uint32_t asbase = s2u(&As[0][0][0]);
    uint32_t bsbase = s2u(&Bs[0][0][0]);

    // preload chunk 0
    #pragma unroll
    for (int l = 0; l < 2; ++l) {
        float4 va = *(const float4*)&A[(size_t)(bm + ar[l]) * K + kb + ac4[l] * 4];
        __nv_bfloat16 h[4], lo[4];
        split_f4(va, h, lo);
        *(uint2*)&As[0][0][ar[l] * PA3 + ac4[l] * 4] = *(uint2*)h;
        *(uint2*)&As[0][1][ar[l] * PA3 + ac4[l] * 4] = *(uint2*)lo;
        float4 vb = *(const float4*)&B[(size_t)(kb + br[l]) * N + bn + bc4[l] * 4];
        split_f4(vb, h, lo);
        *(uint2*)&Bs[0][0][br[l] * PB3 + bc4[l] * 4] = *(uint2*)h;
        *(uint2*)&Bs[0][1][br[l] * PB3 + bc4[l] * 4] = *(uint2*)lo;
    }
    __syncthreads();

    int sub = lane >> 3, lr = lane & 7;
    int cur = 0;
    for (int k0 = 0; k0 < k_len; k0 += BK) {
        float4 pa[2], pb[2];
        bool more = (k0 + BK) < k_len;
        if (more) {
            #pragma unroll
            for (int l = 0; l < 2; ++l) {
                pa[l] = *(const float4*)&A[(size_t)(bm + ar[l]) * K + kb + k0 + BK + ac4[l] * 4];
                pb[l] = *(const float4*)&B[(size_t)(kb + k0 + BK + br[l]) * N + bn + bc4[l] * 4];
            }
        }
        uint32_t ah[2][4], al[2][4], bh[8][2], bl[8][2];
        #pragma unroll
        for (int mt = 0; mt < 2; ++mt) {
            int row = wm + mt * 16 + (sub & 1) * 8 + lr;
            int kc = (sub >> 1) * 8;
            ldsm4(ah[mt], asbase + (uint32_t)((cur * 2 + 0) * BM * PA3 + row * PA3 + kc) * 2);
            ldsm4(al[mt], asbase + (uint32_t)((cur * 2 + 1) * BM * PA3 + row * PA3 + kc) * 2);
        }
        #pragma unroll
        for (int ng = 0; ng < 4; ++ng) {
            int krow = (sub & 1) * 8 + lr;
            int ncol = wn + ng * 16 + (sub >> 1) * 8;
            uint32_t r4[4];
            ldsm4t(r4, bsbase + (uint32_t)((cur * 2 + 0) * BK * PB3 + krow * PB3 + ncol) * 2);
            bh[ng * 2 + 0][0] = r4[0]; bh[ng * 2 + 0][1] = r4[1];
            bh[ng * 2 + 1][0] = r4[2]; bh[ng * 2 + 1][1] = r4[3];
            ldsm4t(r4, bsbase + (uint32_t)((cur * 2 + 1) * BK * PB3 + krow * PB3 + ncol) * 2);
            bl[ng * 2 + 0][0] = r4[0]; bl[ng * 2 + 0][1] = r4[1];
            bl[ng * 2 + 1][0] = r4[2]; bl[ng * 2 + 1][1] = r4[3];
        }
        #pragma unroll
        for (int mt = 0; mt < 2; ++mt)
            #pragma unroll
            for (int nt = 0; nt < 8; ++nt) {
                mma16816(acc[mt][nt], ah[mt], bh[nt]);
                mma16816(acc[mt][nt], ah[mt], bl[nt]);
                mma16816(acc[mt][nt], al[mt], bh[nt]);
            }
        int nb = cur ^ 1;
        if (more) {
            #pragma unroll
            for (int l = 0; l < 2; ++l) {
                __nv_bfloat16 h[4], lo[4];
                split_f4(pa[l], h, lo);
                *(uint2*)&As[nb][0][ar[l] * PA3 + ac4[l] * 4] = *(uint2*)h;
                *(uint2*)&As[nb][1][ar[l] * PA3 + ac4[l] * 4] = *(uint2*)lo;
                split_f4(pb[l], h, lo);
                *(uint2*)&Bs[nb][0][br[l] * PB3 + bc4[l] * 4] = *(uint2*)h;
                *(uint2*)&Bs[nb][1][br[l] * PB3 + bc4[l] * 4] = *(uint2*)lo;
            }
        }
        __syncthreads();
        cur = nb;
    }

    #pragma unroll
    for (int mt = 0; mt < 2; ++mt) {
        int row0 = bm + wm + mt * 16 + (lane >> 2);
        #pragma unroll
        for (int nt = 0; nt < 8; ++nt) {
            int col = bn + wn + nt * 8 + (lane & 3) * 2;
            #pragma unroll
            for (int h = 0; h < 2; ++h) {
                int row = row0 + h * 8;
                *(float2*)&P[(size_t)row * N + col] =
                    make_float2(acc[mt][nt][h * 2 + 0], acc[mt][nt][h * 2 + 1]);
            }
        }
    }
}

// ---------------- split-K reductions ----------------
__global__ __launch_bounds__(256) void red1_kernel(const float* __restrict__ bias) {
    int i = (blockIdx.x * 256 + threadIdx.x) * 4;
    float4 s = *(const float4*)&g_part1[0][i];
    #pragma unroll
    for (int p = 1; p < SPLIT1; ++p) {
        float4 v = *(const float4*)&g_part1[p][i];
        s.x += v.x; s.y += v.y; s.z += v.z; s.w += v.w;
    }
    float4 b = *(const float4*)&bias[i & (HENC - 1)];
    s.x = fmaxf(s.x + b.x, 0.0f); s.y = fmaxf(s.y + b.y, 0.0f);
    s.z = fmaxf(s.z + b.z, 0.0f); s.w = fmaxf(s.w + b.w, 0.0f);
    *(float4*)&g_h1[i] = s;
}
__global__ __launch_bounds__(256) void red2_kernel(const float* __restrict__ bias) {
    int i = (blockIdx.x * 256 + threadIdx.x) * 4;
    float4 s = *(const float4*)&g_part2[0][i];
    #pragma unroll
    for (int p = 1; p < SPLIT2; ++p) {
        float4 v = *(const float4*)&g_part2[p][i];
        s.x += v.x; s.y += v.y; s.z += v.z; s.w += v.w;
    }
    float4 b = *(const float4*)&bias[i & (EMBD - 1)];
    s.x += b.x; s.y += b.y; s.z += b.z; s.w += b.w;
    *(float4*)&g_lat[i] = s;
    __nv_bfloat162 h0 = __floats2bfloat162_rn(s.x, s.y);
    __nv_bfloat162 h1 = __floats2bfloat162_rn(s.z, s.w);
    *(uint2*)&g_lat_bf[i] = make_uint2(*(uint32_t*)&h0, *(uint32_t*)&h1);
}

// ---------------- bf16 tensor-core GEMM (decoder; B converted in-flight) -----
#define PA 40
#define PB 136
template<bool MSE>
__global__ __launch_bounds__(256) void bgemm_kernel(
    const __nv_bfloat16* __restrict__ A, const float* __restrict__ B,
    const float* __restrict__ bias, __nv_bfloat16* __restrict__ Cb,
    const float* __restrict__ X, int M, int N, int K)
{
    const int BM = 128, BN = 128, BK = 32;
    __shared__ __nv_bfloat16 As[2][BM * PA];
    __shared__ __nv_bfloat16 Bs[2][BK * PB];
    int tid = threadIdx.x;
    int wid = tid >> 5, lane = tid & 31;
    int wm = (wid & 3) * 32, wn = (wid >> 2) * 64;
    int bm = blockIdx.y * BM, bn = blockIdx.x * BN;

    float acc[2][8][4];
    #pragma unroll
    for (int mt = 0; mt < 2; ++mt)
        #pragma unroll
        for (int nt = 0; nt < 8; ++nt)
            #pragma unroll
            for (int e = 0; e < 4; ++e) acc[mt][nt][e] = 0.0f;

    int ar[2], acg[2];
    #pragma unroll
    for (int l = 0; l < 2; ++l) { int idx = tid + l * 256; ar[l] = idx >> 2; acg[l] = idx & 3; }
    int br[2], bcg[2];
    #pragma unroll
    for (int l = 0; l < 2; ++l) { int idx = tid + l * 256; br[l] = idx >> 4; bcg[l] = idx & 15; }

    uint32_t asbase = s2u(&As[0][0]);
    uint32_t bsbase = s2u(&Bs[0][0]);

    #pragma unroll
    for (int l = 0; l < 2; ++l) {
        *(uint4*)&As[0][ar[l] * PA + acg[l] * 8] =
            *(const uint4*)&A[(size_t)(bm + ar[l]) * K + acg[l] * 8];
        float4 f0 = *(const float4*)&B[(size_t)br[l] * N + bn + bcg[l] * 8];
        float4 f1 = *(const float4*)&B[(size_t)br[l] * N + bn + bcg[l] * 8 + 4];
        __nv_bfloat162 h[4];
        h[0] = __floats2bfloat162_rn(f0.x, f0.y); h[1] = __floats2bfloat162_rn(f0.z, f0.w);
        h[2] = __floats2bfloat162_rn(f1.x, f1.y); h[3] = __floats2bfloat162_rn(f1.z, f1.w);
        *(uint4*)&Bs[0][br[l] * PB + bcg[l] * 8] = *(uint4*)h;
    }
    __syncthreads();

    int sub = lane >> 3, lr = lane & 7;
    int cur = 0;
    for (int k0 = 0; k0 < K; k0 += BK) {
        uint4 pa[2]; float4 pf0[2], pf1[2];
        bool more = (k0 + BK) < K;
        if (more) {
            #pragma unroll
            for (int l = 0; l < 2; ++l) {
                pa[l] = *(const uint4*)&A[(size_t)(bm + ar[l]) * K + k0 + BK + acg[l] * 8];
                pf0[l] = *(const float4*)&B[(size_t)(k0 + BK + br[l]) * N + bn + bcg[l] * 8];
                pf1[l] = *(const float4*)&B[(size_t)(k0 + BK + br[l]) * N + bn + bcg[l] * 8 + 4];
            }
        }
        #pragma unroll
        for (int ks = 0; ks < BK; ks += 16) {
            uint32_t a[2][4], b[8][2];
            #pragma unroll
            for (int mt = 0; mt < 2; ++mt) {
                int row = wm + mt * 16 + (sub & 1) * 8 + lr;
                int kc = ks + (sub >> 1) * 8;
                ldsm4(a[mt], asbase + (uint32_t)(cur * BM * PA + row * PA + kc) * 2);
            }
            #pragma unroll
            for (int ng = 0; ng < 4; ++ng) {
                uint32_t r4[4];
                int krow = ks + (sub & 1) * 8 + lr;
                int ncol = wn + ng * 16 + (sub >> 1) * 8;
                ldsm4t(r4, bsbase + (uint32_t)(cur * BK * PB + krow * PB + ncol) * 2);
                b[ng * 2 + 0][0] = r4[0]; b[ng * 2 + 0][1] = r4[1];
                b[ng * 2 + 1][0] = r4[2]; b[ng * 2 + 1][1] = r4[3];
            }
            #pragma unroll
            for (int mt = 0; mt < 2; ++mt)
                #pragma unroll
                for (int nt = 0; nt < 8; ++nt)
                    mma16816(acc[mt][nt], a[mt], b[nt]);
        }
        int nb = cur ^ 1;
        if (more) {
            #pragma unroll
            for (int l = 0; l < 2; ++l) {
                *(uint4*)&As[nb][ar[l] * PA + acg[l] * 8] = pa[l];
                __nv_bfloat162 h[4];
                h[0] = __floats2bfloat162_rn(pf0[l].x, pf0[l].y);
                h[1] = __floats2bfloat162_rn(pf0[l].z, pf0[l].w);
                h[2] = __floats2bfloat162_rn(pf1[l].x, pf1[l].y);
                h[3] = __floats2bfloat162_rn(pf1[l].z, pf1[l].w);
                *(uint4*)&Bs[nb][br[l] * PB + bcg[l] * 8] = *(uint4*)h;
            }
        }
        __syncthreads();
        cur = nb;
    }

    float lsum = 0.0f;
    #pragma unroll
    for (int mt = 0; mt < 2; ++mt) {
        int row0 = bm + wm + mt * 16 + (lane >> 2);
        #pragma unroll
        for (int nt = 0; nt < 8; ++nt) {
            int col = bn + wn + nt * 8 + (lane & 3) * 2;
            float b0 = bias[col], b1 = bias[col + 1];
            #pragma unroll
            for (int h = 0; h < 2; ++h) {
                int row = row0 + h * 8;
                float v0 = acc[mt][nt][h * 2 + 0] + b0;
                float v1 = acc[mt][nt][h * 2 + 1] + b1;
                if (!MSE) {
                    v0 = fmaxf(v0, 0.0f); v1 = fmaxf(v1, 0.0f);
                    *(__nv_bfloat162*)&Cb[(size_t)row * N + col] = __floats2bfloat162_rn(v0, v1);
                } else {
                    float2 xv = *(const float2*)&X[(size_t)row * N + col];
                    float d0 = xv.x - v0, d1 = xv.y - v1;
                    lsum = fmaf(d0, d0, lsum);
                    lsum = fmaf(d1, d1, lsum);
                }
            }
        }
    }
    if (MSE) {
        #pragma unroll
        for (int o = 16; o > 0; o >>= 1)
            lsum += __shfl_down_sync(0xffffffffu, lsum, o);
        __shared__ float wsum[8];
        if (lane == 0) wsum[wid] = lsum;
        __syncthreads();
        if (tid == 0) {
            float s = 0.0f;
            #pragma unroll
            for (int w = 0; w < 8; ++w) s += wsum[w];
            atomicAdd(&g_rec, s);
        }
    }
}

// ---------------- pairwise distance matrix per branch ----------------
__global__ __launch_bounds__(256) void dist_kernel() {
    int brz = blockIdx.z;
    int i0 = blockIdx.y * 32, j0 = blockIdx.x * 32;
    __shared__ float Li[32][BRW + 1];
    __shared__ float Lj[32][BRW + 1];
    int t = threadIdx.x;
    #pragma unroll
    for (int l = 0; l < 4; ++l) {
        int idx = t + l * 256;
        int r = idx >> 5, c4 = idx & 31;
        float4 v = *(const float4*)&g_lat[(size_t)(i0 + r) * EMBD + brz * BRW + c4 * 4];
        Li[r][c4 * 4 + 0] = v.x; Li[r][c4 * 4 + 1] = v.y;
        Li[r][c4 * 4 + 2] = v.z; Li[r][c4 * 4 + 3] = v.w;
        float4 w = *(const float4*)&g_lat[(size_t)(j0 + r) * EMBD + brz * BRW + c4 * 4];
        Lj[r][c4 * 4 + 0] = w.x; Lj[r][c4 * 4 + 1] = w.y;
        Lj[r][c4 * 4 + 2] = w.z; Lj[r][c4 * 4 + 3] = w.w;
    }
    __syncthreads();
    int tx = t & 31, ty = t >> 5;
    #pragma unroll
    for (int ii = 0; ii < 4; ++ii) {
        int il = ty * 4 + ii;
        float acc = 0.0f;
        #pragma unroll 16
        for (int k = 0; k < BRW; ++k) {
            float d = Li[il][k] - Lj[tx][k];
            acc = fmaf(d, d, acc);
        }
        g_D[brz][(size_t)(i0 + il) * NPTS + j0 + tx] = sqrtf(acc);
    }
}

// ---------------- Prim MST per branch: ONE WARP, redux-based argmin ----------
// lane owns columns {i*32 + lane}. Exact float bits (nonneg) are u32-monotone.
__global__ __launch_bounds__(32) void prim_kernel() {
    int brz = blockIdx.x;
    const float* __restrict__ D = g_D[brz];
    int lane = threadIdx.x;
    float mind[16];
    unsigned intree = 0;
    #pragma unroll
    for (int i = 0; i < 16; ++i) mind[i] = __ldg(&D[i * 32 + lane]);
    if (lane == 0) intree = 1u;   // vertex 0
    for (int it = 0; it < NPTS - 1; ++it) {
        unsigned lmin = 0xFFFFFFFFu;
        unsigned vb[16];
        #pragma unroll
        for (int i = 0; i < 16; ++i) {
            vb[i] = (intree >> i & 1u) ? 0xFFFFFFFFu : __float_as_uint(mind[i]);
            lmin = min(lmin, vb[i]);
        }
        unsigned vmin = __reduce_min_sync(0xFFFFFFFFu, lmin);
        unsigned lidx = 0xFFFFFFFFu;
        #pragma unroll
        for (int i = 0; i < 16; ++i)
            if (vb[i] == vmin) lidx = min(lidx, (unsigned)(i * 32 + lane));
        unsigned j = __reduce_min_sync(0xFFFFFFFFu, lidx);
        if (lane == 0) g_mst[brz][it] = __uint_as_float(vmin);
        if ((j & 31u) == (unsigned)lane) intree |= 1u << (j >> 5);
        const float* __restrict__ row = D + (size_t)j * NPTS;
        #pragma unroll
        for (int i = 0; i < 16; ++i)
            mind[i] = fminf(mind[i], __ldg(&row[i * 32 + lane]));
    }
}

// ---------------- bitonic sort of MST lengths ----------------
__global__ __launch_bounds__(512) void sort_kernel() {
    int brz = blockIdx.x;
    __shared__ float s[NPTS];
    int t = threadIdx.x;
    s[t] = (t < NPTS - 1) ? g_mst[brz][t] : 3.402823466e38f;
    __syncthreads();
    for (int ksz = 2; ksz <= NPTS; ksz <<= 1) {
        for (int j = ksz >> 1; j > 0; j >>= 1) {
            int ixj = t ^ j;
            if (ixj > t) {
                float a = s[t], b = s[ixj];
                bool up = ((t & ksz) == 0);
                if ((a > b) == up) { s[t] = b; s[ixj] = a; }
            }
            __syncthreads();
        }
    }
    g_mst_sorted[brz][t] = s[t];
}

// ---------------- connectivity loss (binary search over sorted MST) ----------
__global__ __launch_bounds__(256) void conn_kernel() {
    int brz = blockIdx.y;
    __shared__ float s[NPTS];
    int t = threadIdx.x;
    s[t] = g_mst_sorted[brz][t];
    s[t + 256] = g_mst_sorted[brz][t + 256];
    __syncthreads();
    float lsum = 0.0f;
    for (int p = blockIdx.x * 256 + t; p < NPTS * NPTS; p += gridDim.x * 256) {
        int i = p >> 9, j = p & (NPTS - 1);
        if (j > i) {
            float d = g_D[brz][p];
            float lo = d - 0.004f, hi = d + 0.004f;
            int l = 0, r = NPTS;
            while (l < r) {
                int m = (l + r) >> 1;
                if (s[m] < lo) l = m + 1; else r = m;
            }
            bool hit = false;
            while (l < NPTS - 1 && s[l] <= hi) {
                float m = s[l];
                if (fabsf(d - m) <= ATOL_F + RTOL_F * fabsf(m)) { hit = true; break; }
                ++l;
            }
            if (hit) lsum += fabsf(ETA_F - d);
        }
    }
    #pragma unroll
    for (int o = 16; o > 0; o >>= 1)
        lsum += __shfl_down_sync(0xffffffffu, lsum, o);
    __shared__ float wsum[8];
    if ((t & 31) == 0) wsum[t >> 5] = lsum;
    __syncthreads();
    if (t == 0) {
        float ss = 0.0f;
        #pragma unroll
        for (int w = 0; w < 8; ++w) ss += wsum[w];
        atomicAdd(&g_conn, ss);
    }
}

__global__ void final_kernel(float* out) {
    out[0] = g_rec / (float)((size_t)NPTS * (size_t)DIN) + g_conn;
}

// ---------------- launch ----------------
extern "C" void kernel_launch(void* const* d_in, const int* in_sizes, int n_in,
                              void* d_out, int out_size) {
    const float* x   = (const float*)d_in[0];
    const float* We1 = (const float*)d_in[1];
    const float* be1 = (const float*)d_in[2];
    const float* We2 = (const float*)d_in[3];
    const float* be2 = (const float*)d_in[4];
    const float* Wd1 = (const float*)d_in[5];
    const float* bd1 = (const float*)d_in[6];
    const float* Wd2 = (const float*)d_in[7];
    const float* bd2 = (const float*)d_in[8];
    float* out = (float*)d_out;

    float *h1, *p1, *p2;
    __nv_bfloat16 *latb, *h2b;
    cudaGetSymbolAddress((void**)&h1,   g_h1);
    cudaGetSymbolAddress((void**)&p1,   g_part1);
    cudaGetSymbolAddress((void**)&p2,   g_part2);
    cudaGetSymbolAddress((void**)&latb, g_lat_bf);
    cudaGetSymbolAddress((void**)&h2b,  g_h2b);

    // side stream + events for topology/decoder overlap (created once; the
    // enqueued work is identical on every call)
    static cudaStream_t s_top = nullptr;
    static cudaEvent_t ev_fork = nullptr, ev_join = nullptr;
    if (s_top == nullptr) {
        cudaStreamCreate(&s_top);
        cudaEventCreateWithFlags(&ev_fork, cudaEventDisableTiming);
        cudaEventCreateWithFlags(&ev_join, cudaEventDisableTiming);
    }

    zero_kernel<<<1, 1>>>();
    // encoder GEMM1: bf16x3 tensor cores, fused fp32->hi/lo split, split-K 8
    bgemm3_split<<<dim3(HENC / 128, NPTS / 128, SPLIT1), 256>>>(
        x, We1, p1, NPTS, HENC, DIN, DIN / SPLIT1);
    red1_kernel<<<NPTS * HENC / 1024, 256>>>(be1);
    // encoder GEMM2: same bf16x3 kernel, split-K 8
    bgemm3_split<<<dim3(EMBD / 128, NPTS / 128, SPLIT2), 256>>>(
        h1, We2, p2, NPTS, EMBD, HENC, HENC / SPLIT2);
    red2_kernel<<<NPTS * EMBD / 1024, 256>>>(be2);

    // fork: topology chain on side stream, decoder on main stream
    cudaEventRecord(ev_fork, 0);
    cudaStreamWaitEvent(s_top, ev_fork, 0);
    dist_kernel<<<dim3(NPTS / 32, NPTS / 32, NBRANCH), 256, 0, s_top>>>();
    prim_kernel<<<NBRANCH, 32, 0, s_top>>>();
    sort_kernel<<<NBRANCH, NPTS, 0, s_top>>>();
    conn_kernel<<<dim3(64, NBRANCH), 256, 0, s_top>>>();
    cudaEventRecord(ev_join, s_top);

    bgemm_kernel<false><<<dim3(HDEC / 128, NPTS / 128), 256>>>(latb, Wd1, bd1, h2b, nullptr, NPTS, HDEC, EMBD);
    bgemm_kernel<true ><<<dim3(DIN  / 128, NPTS / 128), 256>>>(h2b,  Wd2, bd2, nullptr, x,   NPTS, DIN,  HDEC);

    // join
    cudaStreamWaitEvent(0, ev_join, 0);
    final_kernel<<<1, 1>>>(out);
}

// round 7
// speedup vs baseline: 2.9716x; 1.0053x over previous
#include <cuda_runtime.h>
#include <cuda_bf16.h>
#include <cstdint>

#define NPTS 512
#define DIN 8192
#define HENC 2048
#define EMBD 256
#define HDEC 2048
#define BRW 128
#define NBRANCH 2
#define ETA_F 2.0f
#define RTOL_F 1e-4f
#define ATOL_F 1e-8f
#define SPLIT1 8
#define SPLIT2 8

// ---------------- scratch ----------------
__device__ float g_h1[NPTS * HENC];
__device__ float g_lat[NPTS * EMBD];
__device__ __nv_bfloat16 g_lat_bf[NPTS * EMBD];
__device__ __nv_bfloat16 g_h2b[NPTS * HDEC];
__device__ __nv_bfloat16 g_xhi[NPTS * DIN];
__device__ __nv_bfloat16 g_xlo[NPTS * DIN];
__device__ __nv_bfloat16 g_w1hi[DIN * HENC];
__device__ __nv_bfloat16 g_w1lo[DIN * HENC];
__device__ float g_part1[SPLIT1][NPTS * HENC];
__device__ float g_part2[SPLIT2][NPTS * EMBD];
__device__ float g_D[NBRANCH][NPTS * NPTS];
__device__ float g_mst[NBRANCH][NPTS - 1];
__device__ float g_mst_sorted[NBRANCH][NPTS];
__device__ float g_conn;
__device__ float g_rec;

__global__ void zero_kernel() { g_conn = 0.0f; g_rec = 0.0f; }

// ---------------- helpers ----------------
__device__ __forceinline__ void fma2(unsigned long long& d,
                                     unsigned long long a, unsigned long long b) {
    asm("fma.rn.f32x2 %0, %1, %2, %0;" : "+l"(d) : "l"(a), "l"(b));
}
__device__ __forceinline__ float plo(unsigned long long v) {
    return __uint_as_float((unsigned)(v & 0xffffffffULL));
}
__device__ __forceinline__ float phi(unsigned long long v) {
    return __uint_as_float((unsigned)(v >> 32));
}
__device__ __forceinline__ uint32_t s2u(const void* p) {
    uint32_t a;
    asm("{.reg .u64 t; cvta.to.shared.u64 t, %1; cvt.u32.u64 %0, t;}"
        : "=r"(a) : "l"(p));
    return a;
}
__device__ __forceinline__ void ldsm4(uint32_t* r, uint32_t addr) {
    asm volatile("ldmatrix.sync.aligned.m8n8.x4.shared.b16 {%0,%1,%2,%3}, [%4];"
                 : "=r"(r[0]), "=r"(r[1]), "=r"(r[2]), "=r"(r[3]) : "r"(addr));
}
__device__ __forceinline__ void ldsm4t(uint32_t* r, uint32_t addr) {
    asm volatile("ldmatrix.sync.aligned.m8n8.x4.trans.shared.b16 {%0,%1,%2,%3}, [%4];"
                 : "=r"(r[0]), "=r"(r[1]), "=r"(r[2]), "=r"(r[3]) : "r"(addr));
}
__device__ __forceinline__ void mma16816(float* c, const uint32_t* a, const uint32_t* b) {
    asm volatile(
        "mma.sync.aligned.m16n8k16.row.col.f32.bf16.bf16.f32 "
        "{%0,%1,%2,%3},{%4,%5,%6,%7},{%8,%9},{%0,%1,%2,%3};"
        : "+f"(c[0]), "+f"(c[1]), "+f"(c[2]), "+f"(c[3])
        : "r"(a[0]), "r"(a[1]), "r"(a[2]), "r"(a[3]), "r"(b[0]), "r"(b[1]));
}

// ---------------- fp32 -> (hi, lo) bf16 decomposition, 8 elems/thread ---------
__global__ __launch_bounds__(256) void cvt_split(const float* __restrict__ s,
                                                 __nv_bfloat16* __restrict__ hi,
                                                 __nv_bfloat16* __restrict__ lo, int n)
{
    int i = (blockIdx.x * 256 + threadIdx.x) * 8;
    if (i < n) {
        float4 a = *(const float4*)&s[i];
        float4 b = *(const float4*)&s[i + 4];
        __nv_bfloat16 h[8], l[8];
        float v[8] = {a.x, a.y, a.z, a.w, b.x, b.y, b.z, b.w};
        #pragma unroll
        for (int k = 0; k < 8; ++k) {
            h[k] = __float2bfloat16_rn(v[k]);
            l[k] = __float2bfloat16_rn(v[k] - __bfloat162float(h[k]));
        }
        *(uint4*)&hi[i] = *(uint4*)h;
        *(uint4*)&lo[i] = *(uint4*)l;
    }
}

// ---------------- bf16x3 tensor-core split-K GEMM (fp32-accurate) -------------
// BM=128, BN=128, BK=16, 256 threads (8 warps, 4m x 2n), warp tile 32x64.
// acc += Ahi*Bhi + Ahi*Blo + Alo*Bhi. Writes fp32 partials to P[blockIdx.z].
#define PA3 24
#define PB3 136
__global__ __launch_bounds__(256, 2) void bgemm3_split(
    const __nv_bfloat16* __restrict__ Ahi, const __nv_bfloat16* __restrict__ Alo,
    const __nv_bfloat16* __restrict__ Bhi, const __nv_bfloat16* __restrict__ Blo,
    float* __restrict__ P, int M, int N, int K, int k_len)
{
    const int BM = 128, BN = 128, BK = 16;
    __shared__ __nv_bfloat16 As[2][2][BM * PA3];   // [buf][hi/lo]
    __shared__ __nv_bfloat16 Bs[2][2][BK * PB3];
    int tid = threadIdx.x;
    int wid = tid >> 5, lane = tid & 31;
    int wm = (wid & 3) * 32, wn = (wid >> 2) * 64;
    int bm = blockIdx.y * BM, bn = blockIdx.x * BN;
    int kb = blockIdx.z * k_len;
    P += (size_t)blockIdx.z * M * N;

    float acc[2][8][4];
    #pragma unroll
    for (int mt = 0; mt < 2; ++mt)
        #pragma unroll
        for (int nt = 0; nt < 8; ++nt)
            #pragma unroll
            for (int e = 0; e < 4; ++e) acc[mt][nt][e] = 0.0f;

    int ar = tid >> 1, acg = tid & 1;       // A tile 128x16 = 256 uint4
    int br = tid >> 4, bcg = tid & 15;      // B tile 16x128 = 256 uint4

    uint32_t asbase = s2u(&As[0][0][0]);
    uint32_t bsbase = s2u(&Bs[0][0][0]);

    *(uint4*)&As[0][0][ar * PA3 + acg * 8] =
        *(const uint4*)&Ahi[(size_t)(bm + ar) * K + kb + acg * 8];
    *(uint4*)&As[0][1][ar * PA3 + acg * 8] =
        *(const uint4*)&Alo[(size_t)(bm + ar) * K + kb + acg * 8];
    *(uint4*)&Bs[0][0][br * PB3 + bcg * 8] =
        *(const uint4*)&Bhi[(size_t)(kb + br) * N + bn + bcg * 8];
    *(uint4*)&Bs[0][1][br * PB3 + bcg * 8] =
        *(const uint4*)&Blo[(size_t)(kb + br) * N + bn + bcg * 8];
    __syncthreads();

    int sub = lane >> 3, lr = lane & 7;
    int cur = 0;
    for (int k0 = 0; k0 < k_len; k0 += BK) {
        uint4 pah, pal, pbh, pbl;
        bool more = (k0 + BK) < k_len;
        if (more) {
            pah = *(const uint4*)&Ahi[(size_t)(bm + ar) * K + kb + k0 + BK + acg * 8];
            pal = *(const uint4*)&Alo[(size_t)(bm + ar) * K + kb + k0 + BK + acg * 8];
            pbh = *(const uint4*)&Bhi[(size_t)(kb + k0 + BK + br) * N + bn + bcg * 8];
            pbl = *(const uint4*)&Blo[(size_t)(kb + k0 + BK + br) * N + bn + bcg * 8];
        }
        uint32_t ah[2][4], al[2][4], bh[8][2], bl[8][2];
        #pragma unroll
        for (int mt = 0; mt < 2; ++mt) {
            int row = wm + mt * 16 + (sub & 1) * 8 + lr;
            int kc = (sub >> 1) * 8;
            ldsm4(ah[mt], asbase + (uint32_t)((cur * 2 + 0) * BM * PA3 + row * PA3 + kc) * 2);
            ldsm4(al[mt], asbase + (uint32_t)((cur * 2 + 1) * BM * PA3 + row * PA3 + kc) * 2);
        }
        #pragma unroll
        for (int ng = 0; ng < 4; ++ng) {
            int krow = (sub & 1) * 8 + lr;
            int ncol = wn + ng * 16 + (sub >> 1) * 8;
            uint32_t r4[4];
            ldsm4t(r4, bsbase + (uint32_t)((cur * 2 + 0) * BK * PB3 + krow * PB3 + ncol) * 2);
            bh[ng * 2 + 0][0] = r4[0]; bh[ng * 2 + 0][1] = r4[1];
            bh[ng * 2 + 1][0] = r4[2]; bh[ng * 2 + 1][1] = r4[3];
            ldsm4t(r4, bsbase + (uint32_t)((cur * 2 + 1) * BK * PB3 + krow * PB3 + ncol) * 2);
            bl[ng * 2 + 0][0] = r4[0]; bl[ng * 2 + 0][1] = r4[1];
            bl[ng * 2 + 1][0] = r4[2]; bl[ng * 2 + 1][1] = r4[3];
        }
        #pragma unroll
        for (int mt = 0; mt < 2; ++mt)
            #pragma unroll
            for (int nt = 0; nt < 8; ++nt) {
                mma16816(acc[mt][nt], ah[mt], bh[nt]);
                mma16816(acc[mt][nt], ah[mt], bl[nt]);
                mma16816(acc[mt][nt], al[mt], bh[nt]);
            }
        int nb = cur ^ 1;
        if (more) {
            *(uint4*)&As[nb][0][ar * PA3 + acg * 8] = pah;
            *(uint4*)&As[nb][1][ar * PA3 + acg * 8] = pal;
            *(uint4*)&Bs[nb][0][br * PB3 + bcg * 8] = pbh;
            *(uint4*)&Bs[nb][1][br * PB3 + bcg * 8] = pbl;
        }
        __syncthreads();
        cur = nb;
    }

    #pragma unroll
    for (int mt = 0; mt < 2; ++mt) {
        int row0 = bm + wm + mt * 16 + (lane >> 2);
        #pragma unroll
        for (int nt = 0; nt < 8; ++nt) {
            int col = bn + wn + nt * 8 + (lane & 3) * 2;
            #pragma unroll
            for (int h = 0; h < 2; ++h) {
                int row = row0 + h * 8;
                *(float2*)&P[(size_t)row * N + col] =
                    make_float2(acc[mt][nt][h * 2 + 0], acc[mt][nt][h * 2 + 1]);
            }
        }
    }
}

// ---------------- fp32 split-K GEMM via packed f32x2 FMA (GEMM2) -------------
#define PAD2 (2 * 64 + 2)
template<int G>
__global__ __launch_bounds__(256) void sgemm_split(
    const float* __restrict__ A, const float* __restrict__ B,
    float* __restrict__ P, int M, int N, int K, int k_len)
{
    const int BM = 64, BK = 16, BN = 64 * G;
    __shared__ __align__(16) float As2[2][BK][PAD2];
    __shared__ __align__(16) float Bs[2][BK][BN];
    int tid = threadIdx.x;
    int ty = tid >> 4, tx = tid & 15;
    int bm = blockIdx.y * BM, bn = blockIdx.x * BN;
    int kb = blockIdx.z * k_len;
    P += (size_t)blockIdx.z * M * N;

    unsigned long long acc[4][2 * G];
    #pragma unroll
    for (int r = 0; r < 4; ++r)
        #pragma unroll
        for (int c = 0; c < 2 * G; ++c) acc[r][c] = 0ULL;

    int arow = tid >> 2, ak4 = tid & 3;
    const int F4PR = BN / 4;
    int brow[G], bc[G];
    #pragma unroll
    for (int l = 0; l < G; ++l) { int idx = tid + l * 256; brow[l] = idx / F4PR; bc[l] = idx % F4PR; }

    {
        float4 v = *(const float4*)&A[(size_t)(bm + arow) * K + kb + ak4 * 4];
        As2[0][ak4 * 4 + 0][2 * arow] = v.x; As2[0][ak4 * 4 + 0][2 * arow + 1] = v.x;
        As2[0][ak4 * 4 + 1][2 * arow] = v.y; As2[0][ak4 * 4 + 1][2 * arow + 1] = v.y;
        As2[0][ak4 * 4 + 2][2 * arow] = v.z; As2[0][ak4 * 4 + 2][2 * arow + 1] = v.z;
        As2[0][ak4 * 4 + 3][2 * arow] = v.w; As2[0][ak4 * 4 + 3][2 * arow + 1] = v.w;
        #pragma unroll
        for (int l = 0; l < G; ++l)
            *(float4*)&Bs[0][brow[l]][bc[l] * 4] =
                *(const float4*)&B[(size_t)(kb + brow[l]) * N + bn + bc[l] * 4];
    }
    __syncthreads();

    int cur = 0;
    for (int k0 = 0; k0 < k_len; k0 += BK) {
        float4 pa; float4 pb[G];
        bool more = (k0 + BK) < k_len;
        if (more) {
            pa = *(const float4*)&A[(size_t)(bm + arow) * K + kb + k0 + BK + ak4 * 4];
            #pragma unroll
            for (int l = 0; l < G; ++l)
                pb[l] = *(const float4*)&B[(size_t)(kb + k0 + BK + brow[l]) * N + bn + bc[l] * 4];
        }
        #pragma unroll
        for (int k = 0; k < BK; ++k) {
            unsigned long long a2[4];
            #pragma unroll
            for (int r = 0; r < 4; ++r)
                a2[r] = *(const unsigned long long*)&As2[cur][k][2 * (ty * 4 + r)];
            #pragma unroll
            for (int g = 0; g < G; ++g) {
                unsigned long long b0 = *(const unsigned long long*)&Bs[cur][k][g * 64 + tx * 4];
                unsigned long long b1 = *(const unsigned long long*)&Bs[cur][k][g * 64 + tx * 4 + 2];
                #pragma unroll
                for (int r = 0; r < 4; ++r) {
                    fma2(acc[r][g * 2 + 0], a2[r], b0);
                    fma2(acc[r][g * 2 + 1], a2[r], b1);
                }
            }
        }
        int nb = cur ^ 1;
        if (more) {
            As2[nb][ak4 * 4 + 0][2 * arow] = pa.x; As2[nb][ak4 * 4 + 0][2 * arow + 1] = pa.x;
            As2[nb][ak4 * 4 + 1][2 * arow] = pa.y; As2[nb][ak4 * 4 + 1][2 * arow + 1] = pa.y;
            As2[nb][ak4 * 4 + 2][2 * arow] = pa.z; As2[nb][ak4 * 4 + 2][2 * arow + 1] = pa.z;
            As2[nb][ak4 * 4 + 3][2 * arow] = pa.w; As2[nb][ak4 * 4 + 3][2 * arow + 1] = pa.w;
            #pragma unroll
            for (int l = 0; l < G; ++l)
                *(float4*)&Bs[nb][brow[l]][bc[l] * 4] = pb[l];
        }
        __syncthreads();
        cur = nb;
    }

    #pragma unroll
    for (int r = 0; r < 4; ++r) {
        int row = bm + ty * 4 + r;
        #pragma unroll
        for (int g = 0; g < G; ++g) {
            int cbase = bn + g * 64 + tx * 4;
            float4 o;
            o.x = plo(acc[r][g * 2 + 0]); o.y = phi(acc[r][g * 2 + 0]);
            o.z = plo(acc[r][g * 2 + 1]); o.w = phi(acc[r][g * 2 + 1]);
            *(float4*)&P[(size_t)row * N + cbase] = o;
        }
    }
}

// ---------------- split-K reductions ----------------
__global__ __launch_bounds__(256) void red1_kernel(const float* __restrict__ bias) {
    int i = (blockIdx.x * 256 + threadIdx.x) * 4;
    float4 s = *(const float4*)&g_part1[0][i];
    #pragma unroll
    for (int p = 1; p < SPLIT1; ++p) {
        float4 v = *(const float4*)&g_part1[p][i];
        s.x += v.x; s.y += v.y; s.z += v.z; s.w += v.w;
    }
    float4 b = *(const float4*)&bias[i & (HENC - 1)];
    s.x = fmaxf(s.x + b.x, 0.0f); s.y = fmaxf(s.y + b.y, 0.0f);
    s.z = fmaxf(s.z + b.z, 0.0f); s.w = fmaxf(s.w + b.w, 0.0f);
    *(float4*)&g_h1[i] = s;
}
__global__ __launch_bounds__(256) void red2_kernel(const float* __restrict__ bias) {
    int i = (blockIdx.x * 256 + threadIdx.x) * 4;
    float4 s = *(const float4*)&g_part2[0][i];
    #pragma unroll
    for (int p = 1; p < SPLIT2; ++p) {
        float4 v = *(const float4*)&g_part2[p][i];
        s.x += v.x; s.y += v.y; s.z += v.z; s.w += v.w;
    }
    float4 b = *(const float4*)&bias[i & (EMBD - 1)];
    s.x += b.x; s.y += b.y; s.z += b.z; s.w += b.w;
    *(float4*)&g_lat[i] = s;
    __nv_bfloat162 h0 = __floats2bfloat162_rn(s.x, s.y);
    __nv_bfloat162 h1 = __floats2bfloat162_rn(s.z, s.w);
    *(uint2*)&g_lat_bf[i] = make_uint2(*(uint32_t*)&h0, *(uint32_t*)&h1);
}

// ---------------- bf16 tensor-core GEMM (decoder; B converted in-flight) -----
#define PA 40
#define PB 136
template<bool MSE>
__global__ __launch_bounds__(256) void bgemm_kernel(
    const __nv_bfloat16* __restrict__ A, const float* __restrict__ B,
    const float* __restrict__ bias, __nv_bfloat16* __restrict__ Cb,
    const float* __restrict__ X, int M, int N, int K)
{
    const int BM = 128, BN = 128, BK = 32;
    __shared__ __nv_bfloat16 As[2][BM * PA];
    __shared__ __nv_bfloat16 Bs[2][BK * PB];
    int tid = threadIdx.x;
    int wid = tid >> 5, lane = tid & 31;
    int wm = (wid & 3) * 32, wn = (wid >> 2) * 64;
    int bm = blockIdx.y * BM, bn = blockIdx.x * BN;

    float acc[2][8][4];
    #pragma unroll
    for (int mt = 0; mt < 2; ++mt)
        #pragma unroll
        for (int nt = 0; nt < 8; ++nt)
            #pragma unroll
            for (int e = 0; e < 4; ++e) acc[mt][nt][e] = 0.0f;

    int ar[2], acg[2];
    #pragma unroll
    for (int l = 0; l < 2; ++l) { int idx = tid + l * 256; ar[l] = idx >> 2; acg[l] = idx & 3; }
    int br[2], bcg[2];
    #pragma unroll
    for (int l = 0; l < 2; ++l) { int idx = tid + l * 256; br[l] = idx >> 4; bcg[l] = idx & 15; }

    uint32_t asbase = s2u(&As[0][0]);
    uint32_t bsbase = s2u(&Bs[0][0]);

    #pragma unroll
    for (int l = 0; l < 2; ++l) {
        *(uint4*)&As[0][ar[l] * PA + acg[l] * 8] =
            *(const uint4*)&A[(size_t)(bm + ar[l]) * K + acg[l] * 8];
        float4 f0 = *(const float4*)&B[(size_t)br[l] * N + bn + bcg[l] * 8];
        float4 f1 = *(const float4*)&B[(size_t)br[l] * N + bn + bcg[l] * 8 + 4];
        __nv_bfloat162 h[4];
        h[0] = __floats2bfloat162_rn(f0.x, f0.y); h[1] = __floats2bfloat162_rn(f0.z, f0.w);
        h[2] = __floats2bfloat162_rn(f1.x, f1.y); h[3] = __floats2bfloat162_rn(f1.z, f1.w);
        *(uint4*)&Bs[0][br[l] * PB + bcg[l] * 8] = *(uint4*)h;
    }
    __syncthreads();

    int sub = lane >> 3, lr = lane & 7;
    int cur = 0;
    for (int k0 = 0; k0 < K; k0 += BK) {
        uint4 pa[2]; float4 pf0[2], pf1[2];
        bool more = (k0 + BK) < K;
        if (more) {
            #pragma unroll
            for (int l = 0; l < 2; ++l) {
                pa[l] = *(const uint4*)&A[(size_t)(bm + ar[l]) * K + k0 + BK + acg[l] * 8];
                pf0[l] = *(const float4*)&B[(size_t)(k0 + BK + br[l]) * N + bn + bcg[l] * 8];
                pf1[l] = *(const float4*)&B[(size_t)(k0 + BK + br[l]) * N + bn + bcg[l] * 8 + 4];
            }
        }
        #pragma unroll
        for (int ks = 0; ks < BK; ks += 16) {
            uint32_t a[2][4], b[8][2];
            #pragma unroll
            for (int mt = 0; mt < 2; ++mt) {
                int row = wm + mt * 16 + (sub & 1) * 8 + lr;
                int kc = ks + (sub >> 1) * 8;
                ldsm4(a[mt], asbase + (uint32_t)(cur * BM * PA + row * PA + kc) * 2);
            }
            #pragma unroll
            for (int ng = 0; ng < 4; ++ng) {
                uint32_t r4[4];
                int krow = ks + (sub & 1) * 8 + lr;
                int ncol = wn + ng * 16 + (sub >> 1) * 8;
                ldsm4t(r4, bsbase + (uint32_t)(cur * BK * PB + krow * PB + ncol) * 2);
                b[ng * 2 + 0][0] = r4[0]; b[ng * 2 + 0][1] = r4[1];
                b[ng * 2 + 1][0] = r4[2]; b[ng * 2 + 1][1] = r4[3];
            }
            #pragma unroll
            for (int mt = 0; mt < 2; ++mt)
                #pragma unroll
                for (int nt = 0; nt < 8; ++nt)
                    mma16816(acc[mt][nt], a[mt], b[nt]);
        }
        int nb = cur ^ 1;
        if (more) {
            #pragma unroll
            for (int l = 0; l < 2; ++l) {
                *(uint4*)&As[nb][ar[l] * PA + acg[l] * 8] = pa[l];
                __nv_bfloat162 h[4];
                h[0] = __floats2bfloat162_rn(pf0[l].x, pf0[l].y);
                h[1] = __floats2bfloat162_rn(pf0[l].z, pf0[l].w);
                h[2] = __floats2bfloat162_rn(pf1[l].x, pf1[l].y);
                h[3] = __floats2bfloat162_rn(pf1[l].z, pf1[l].w);
                *(uint4*)&Bs[nb][br[l] * PB + bcg[l] * 8] = *(uint4*)h;
            }
        }
        __syncthreads();
        cur = nb;
    }

    float lsum = 0.0f;
    #pragma unroll
    for (int mt = 0; mt < 2; ++mt) {
        int row0 = bm + wm + mt * 16 + (lane >> 2);
        #pragma unroll
        for (int nt = 0; nt < 8; ++nt) {
            int col = bn + wn + nt * 8 + (lane & 3) * 2;
            float b0 = bias[col], b1 = bias[col + 1];
            #pragma unroll
            for (int h = 0; h < 2; ++h) {
                int row = row0 + h * 8;
                float v0 = acc[mt][nt][h * 2 + 0] + b0;
                float v1 = acc[mt][nt][h * 2 + 1] + b1;
                if (!MSE) {
                    v0 = fmaxf(v0, 0.0f); v1 = fmaxf(v1, 0.0f);
                    *(__nv_bfloat162*)&Cb[(size_t)row * N + col] = __floats2bfloat162_rn(v0, v1);
                } else {
                    float2 xv = *(const float2*)&X[(size_t)row * N + col];
                    float d0 = xv.x - v0, d1 = xv.y - v1;
                    lsum = fmaf(d0, d0, lsum);
                    lsum = fmaf(d1, d1, lsum);
                }
            }
        }
    }
    if (MSE) {
        #pragma unroll
        for (int o = 16; o > 0; o >>= 1)
            lsum += __shfl_down_sync(0xffffffffu, lsum, o);
        __shared__ float wsum[8];
        if (lane == 0) wsum[wid] = lsum;
        __syncthreads();
        if (tid == 0) {
            float s = 0.0f;
            #pragma unroll
            for (int w = 0; w < 8; ++w) s += wsum[w];
            atomicAdd(&g_rec, s);
        }
    }
}

// ---------------- pairwise distance matrix per branch ----------------
__global__ __launch_bounds__(256) void dist_kernel() {
    int brz = blockIdx.z;
    int i0 = blockIdx.y * 32, j0 = blockIdx.x * 32;
    __shared__ float Li[32][BRW + 1];
    __shared__ float Lj[32][BRW + 1];
    int t = threadIdx.x;
    #pragma unroll
    for (int l = 0; l < 4; ++l) {
        int idx = t + l * 256;
        int r = idx >> 5, c4 = idx & 31;
        float4 v = *(const float4*)&g_lat[(size_t)(i0 + r) * EMBD + brz * BRW + c4 * 4];
        Li[r][c4 * 4 + 0] = v.x; Li[r][c4 * 4 + 1] = v.y;
        Li[r][c4 * 4 + 2] = v.z; Li[r][c4 * 4 + 3] = v.w;
        float4 w = *(const float4*)&g_lat[(size_t)(j0 + r) * EMBD + brz * BRW + c4 * 4];
        Lj[r][c4 * 4 + 0] = w.x; Lj[r][c4 * 4 + 1] = w.y;
        Lj[r][c4 * 4 + 2] = w.z; Lj[r][c4 * 4 + 3] = w.w;
    }
    __syncthreads();
    int tx = t & 31, ty = t >> 5;
    #pragma unroll
    for (int ii = 0; ii < 4; ++ii) {
        int il = ty * 4 + ii;
        float acc = 0.0f;
        #pragma unroll 16
        for (int k = 0; k < BRW; ++k) {
            float d = Li[il][k] - Lj[tx][k];
            acc = fmaf(d, d, acc);
        }
        g_D[brz][(size_t)(i0 + il) * NPTS + j0 + tx] = sqrtf(acc);
    }
}

// ---------------- Prim MST per branch: ONE WARP, redux-based argmin ----------
__global__ __launch_bounds__(32) void prim_kernel() {
    int brz = blockIdx.x;
    const float* __restrict__ D = g_D[brz];
    int lane = threadIdx.x;
    float mind[16];
    unsigned intree = 0;
    #pragma unroll
    for (int i = 0; i < 16; ++i) mind[i] = __ldg(&D[i * 32 + lane]);
    if (lane == 0) intree = 1u;
    for (int it = 0; it < NPTS - 1; ++it) {
        unsigned lmin = 0xFFFFFFFFu;
        unsigned vb[16];
        #pragma unroll
        for (int i = 0; i < 16; ++i) {
            vb[i] = (intree >> i & 1u) ? 0xFFFFFFFFu : __float_as_uint(mind[i]);
            lmin = min(lmin, vb[i]);
        }
        unsigned vmin = __reduce_min_sync(0xFFFFFFFFu, lmin);
        unsigned lidx = 0xFFFFFFFFu;
        #pragma unroll
        for (int i = 0; i < 16; ++i)
            if (vb[i] == vmin) lidx = min(lidx, (unsigned)(i * 32 + lane));
        unsigned j = __reduce_min_sync(0xFFFFFFFFu, lidx);
        if (lane == 0) g_mst[brz][it] = __uint_as_float(vmin);
        if ((j & 31u) == (unsigned)lane) intree |= 1u << (j >> 5);
        const float* __restrict__ row = D + (size_t)j * NPTS;
        #pragma unroll
        for (int i = 0; i < 16; ++i)
            mind[i] = fminf(mind[i], __ldg(&row[i * 32 + lane]));
    }
}

// ---------------- bitonic sort of MST lengths ----------------
__global__ __launch_bounds__(512) void sort_kernel() {
    int brz = blockIdx.x;
    __shared__ float s[NPTS];
    int t = threadIdx.x;
    s[t] = (t < NPTS - 1) ? g_mst[brz][t] : 3.402823466e38f;
    __syncthreads();
    for (int ksz = 2; ksz <= NPTS; ksz <<= 1) {
        for (int j = ksz >> 1; j > 0; j >>= 1) {
            int ixj = t ^ j;
            if (ixj > t) {
                float a = s[t], b = s[ixj];
                bool up = ((t & ksz) == 0);
                if ((a > b) == up) { s[t] = b; s[ixj] = a; }
            }
            __syncthreads();
        }
    }
    g_mst_sorted[brz][t] = s[t];
}

// ---------------- connectivity loss (binary search over sorted MST) ----------
__global__ __launch_bounds__(256) void conn_kernel() {
    int brz = blockIdx.y;
    __shared__ float s[NPTS];
    int t = threadIdx.x;
    s[t] = g_mst_sorted[brz][t];
    s[t + 256] = g_mst_sorted[brz][t + 256];
    __syncthreads();
    float lsum = 0.0f;
    for (int p = blockIdx.x * 256 + t; p < NPTS * NPTS; p += gridDim.x * 256) {
        int i = p >> 9, j = p & (NPTS - 1);
        if (j > i) {
            float d = g_D[brz][p];
            float lo = d - 0.004f, hi = d + 0.004f;
            int l = 0, r = NPTS;
            while (l < r) {
                int m = (l + r) >> 1;
                if (s[m] < lo) l = m + 1; else r = m;
            }
            bool hit = false;
            while (l < NPTS - 1 && s[l] <= hi) {
                float m = s[l];
                if (fabsf(d - m) <= ATOL_F + RTOL_F * fabsf(m)) { hit = true; break; }
                ++l;
            }
            if (hit) lsum += fabsf(ETA_F - d);
        }
    }
    #pragma unroll
    for (int o = 16; o > 0; o >>= 1)
        lsum += __shfl_down_sync(0xffffffffu, lsum, o);
    __shared__ float wsum[8];
    if ((t & 31) == 0) wsum[t >> 5] = lsum;
    __syncthreads();
    if (t == 0) {
        float ss = 0.0f;
        #pragma unroll
        for (int w = 0; w < 8; ++w) ss += wsum[w];
        atomicAdd(&g_conn, ss);
    }
}

__global__ void final_kernel(float* out) {
    out[0] = g_rec / (float)((size_t)NPTS * (size_t)DIN) + g_conn;
}

// ---------------- launch ----------------
extern "C" void kernel_launch(void* const* d_in, const int* in_sizes, int n_in,
                              void* d_out, int out_size) {
    const float* x   = (const float*)d_in[0];
    const float* We1 = (const float*)d_in[1];
    const float* be1 = (const float*)d_in[2];
    const float* We2 = (const float*)d_in[3];
    const float* be2 = (const float*)d_in[4];
    const float* Wd1 = (const float*)d_in[5];
    const float* bd1 = (const float*)d_in[6];
    const float* Wd2 = (const float*)d_in[7];
    const float* bd2 = (const float*)d_in[8];
    float* out = (float*)d_out;

    float *h1, *p1, *p2;
    __nv_bfloat16 *latb, *h2b, *xhi, *xlo, *w1hi, *w1lo;
    cudaGetSymbolAddress((void**)&h1,   g_h1);
    cudaGetSymbolAddress((void**)&p1,   g_part1);
    cudaGetSymbolAddress((void**)&p2,   g_part2);
    cudaGetSymbolAddress((void**)&latb, g_lat_bf);
    cudaGetSymbolAddress((void**)&h2b,  g_h2b);
    cudaGetSymbolAddress((void**)&xhi,  g_xhi);
    cudaGetSymbolAddress((void**)&xlo,  g_xlo);
    cudaGetSymbolAddress((void**)&w1hi, g_w1hi);
    cudaGetSymbolAddress((void**)&w1lo, g_w1lo);

    static cudaStream_t s_top = nullptr;
    static cudaEvent_t ev_fork = nullptr, ev_join = nullptr;
    if (s_top == nullptr) {
        cudaStreamCreate(&s_top);
        cudaEventCreateWithFlags(&ev_fork, cudaEventDisableTiming);
        cudaEventCreateWithFlags(&ev_join, cudaEventDisableTiming);
    }

    zero_kernel<<<1, 1>>>();
    // hi/lo decomposition (done once, DRAM-bound)
    cvt_split<<<(NPTS * DIN) / 2048, 256>>>(x, xhi, xlo, NPTS * DIN);
    cvt_split<<<(DIN * HENC) / 2048, 256>>>(We1, w1hi, w1lo, DIN * HENC);
    // encoder GEMM1: bf16x3 tensor cores, split-K 8, 2 CTAs/SM
    bgemm3_split<<<dim3(HENC / 128, NPTS / 128, SPLIT1), 256>>>(
        xhi, xlo, w1hi, w1lo, p1, NPTS, HENC, DIN, DIN / SPLIT1);
    red1_kernel<<<NPTS * HENC / 1024, 256>>>(be1);
    // encoder GEMM2: fp32 FFMA2 split-K (precision safety)
    sgemm_split<1><<<dim3(EMBD / 64, NPTS / 64, SPLIT2), 256>>>(h1, We2, p2, NPTS, EMBD, HENC, HENC / SPLIT2);
    red2_kernel<<<NPTS * EMBD / 1024, 256>>>(be2);

    // fork: topology chain on side stream, decoder on main stream
    cudaEventRecord(ev_fork, 0);
    cudaStreamWaitEvent(s_top, ev_fork, 0);
    dist_kernel<<<dim3(NPTS / 32, NPTS / 32, NBRANCH), 256, 0, s_top>>>();
    prim_kernel<<<NBRANCH, 32, 0, s_top>>>();
    sort_kernel<<<NBRANCH, NPTS, 0, s_top>>>();
    conn_kernel<<<dim3(64, NBRANCH), 256, 0, s_top>>>();
    cudaEventRecord(ev_join, s_top);

    bgemm_kernel<false><<<dim3(HDEC / 128, NPTS / 128), 256>>>(latb, Wd1, bd1, h2b, nullptr, NPTS, HDEC, EMBD);
    bgemm_kernel<true ><<<dim3(DIN  / 128, NPTS / 128), 256>>>(h2b,  Wd2, bd2, nullptr, x,   NPTS, DIN,  HDEC);

    cudaStreamWaitEvent(0, ev_join, 0);
    final_kernel<<<1, 1>>>(out);
}